// round 13
// baseline (speedup 1.0000x reference)
#include <cuda_runtime.h>
#include <cuda_bf16.h>
#include <cuda_fp16.h>
#include <cstdint>

// ---------------------------------------------------------------------------
// Problem constants
// ---------------------------------------------------------------------------
#define D_MODEL 1024
#define BATCH   16
#define LQ      1024
#define NBE     256
#define ML (BATCH * LQ)    // 16384
#define MB (BATCH * NBE)   // 4096

// ---------------------------------------------------------------------------
// Scratch (__device__ globals; no allocation anywhere)
// ---------------------------------------------------------------------------
__device__ __half  g_qh  [ML * D_MODEL];                 // query fp16 (1 plane)
__device__ __half  g_A12h[2048 * D_MODEL];               // [WQ^T ; WO] hi plane
__device__ __half  g_A12l[2048 * D_MODEL];               // lo plane (bias vectors only)
__device__ __half  g_WKTh[D_MODEL * D_MODEL];            // WK^T hi
__device__ __half  g_WKTl[D_MODEL * D_MODEL];            // WK^T lo (bias vectors only)
__device__ __half  g_Gh  [MB * D_MODEL];                 // gathered ents (1 plane)
__device__ __half  g_T12 [2048 * D_MODEL];               // [T1; T2] fp16
__device__ __half  g_EQEO[MB * 2048];                    // [EQ | EO] fp16
__device__ __half  g_EOT [MB * D_MODEL];                 // EO^T per batch
__device__ float   g_sb  [MB];                           // bQ.ENT score bias
__device__ float   g_vb  [1025];                         // WK^T bQ, [1024]=bQ.bK
__device__ float   g_b2  [2048];                         // [bK@WQ | bK@WO^T]
__device__ __half  g_Wh  [ML * NBE];                     // softmax wts fp16 (1 plane)
__device__ float   g_P   [ML * D_MODEL];                 // pre-LN fp32

// ---------------------------------------------------------------------------
// Helpers
// ---------------------------------------------------------------------------
__device__ __forceinline__ void split1h(float x, __half& h, __half& l) {
    h = __float2half_rn(x);
    l = __float2half_rn(x - __half2float(h));
}

__device__ __forceinline__ void cp16(uint32_t dst, const void* src) {
    asm volatile("cp.async.cg.shared.global [%0], [%1], 16;"
                 :: "r"(dst), "l"(src) : "memory");
}
__device__ __forceinline__ void ldsm4(uint32_t* r, uint32_t addr) {
    asm volatile("ldmatrix.sync.aligned.m8n8.x4.shared.b16 {%0,%1,%2,%3}, [%4];"
                 : "=r"(r[0]), "=r"(r[1]), "=r"(r[2]), "=r"(r[3]) : "r"(addr));
}
__device__ __forceinline__ void mma_f16(float* c, const uint32_t* a,
                                        uint32_t b0, uint32_t b1) {
    asm volatile(
        "mma.sync.aligned.m16n8k16.row.col.f32.f16.f16.f32 "
        "{%0,%1,%2,%3}, {%4,%5,%6,%7}, {%8,%9}, {%0,%1,%2,%3};"
        : "+f"(c[0]), "+f"(c[1]), "+f"(c[2]), "+f"(c[3])
        : "r"(a[0]), "r"(a[1]), "r"(a[2]), "r"(a[3]), "r"(b0), "r"(b1));
}

// ---------------------------------------------------------------------------
// gemm2: fp16 NT GEMM (1-term): C[bz][M,N] = A @ B^T (+bias)
// A fp16 plane (lda=K), B fp16 plane (row stride ldb).
// CTA 128x128, BK=64 (SKB64=144B conflict-free rows), 8 warps (2x4),
// 2-stage cp.async pipeline, 256 threads, 2 CTAs/SM.
// ---------------------------------------------------------------------------
#define SKB64 144                      // 64 halves (128B) + 16B pad
#define PLANE64 (128 * SKB64)          // 18432 B
#define STAGE64 (2 * PLANE64)          // A + B = 36864 B
#define GSMEM64 (2 * STAGE64)          // 73728 B

template<bool F16OUT>
__global__ void __launch_bounds__(256, 2) gemm2(
    const __half* __restrict__ Ap, long sA,
    const __half* __restrict__ Bp, long sB, int ldb,
    float* __restrict__ Cf, __half* __restrict__ Ch, long sC,
    int N, int K,
    const float* __restrict__ bias, long sBias)
{
    extern __shared__ char smc[];
    const uint32_t smb = (uint32_t)__cvta_generic_to_shared(smc);

    const int tid  = threadIdx.x;
    const int wid  = tid >> 5;
    const int lane = tid & 31;
    const int wm   = wid >> 2;
    const int wn   = wid & 3;
    const int gq   = lane >> 2;
    const int tg   = lane & 3;

    const int mtile = blockIdx.y * 128;
    const int ntile = blockIdx.x * 128;
    const int bz    = blockIdx.z;
    Ap += (long)bz * sA;
    Bp += (long)bz * sB;

    const int nch = K >> 6;           // K / 64

    float acc[4][4][4];
#pragma unroll
    for (int i = 0; i < 4; i++)
#pragma unroll
        for (int j = 0; j < 4; j++)
#pragma unroll
            for (int q = 0; q < 4; q++) acc[i][j][q] = 0.f;

    // loader: per plane 128 rows x 8 segs(16B) = 1024 slots; 256 thr x 4 segs
    const int lrow = tid >> 1;            // 0..127
    const int lseg = (tid & 1) * 4;       // seg 0..3 or 4..7
    const long aoff = (long)(mtile + lrow) * K + lseg * 8;
    const long boff = (long)(ntile + lrow) * ldb + lseg * 8;
    const uint32_t sdst = lrow * SKB64 + lseg * 16;

    auto load_chunk = [&](int c, int s) {
        const long kofs = (long)c * 64;
        const uint32_t sa = smb + s * STAGE64 + sdst;
        const uint32_t sbm = sa + PLANE64;
#pragma unroll
        for (int i = 0; i < 4; i++) {
            cp16(sa  + i * 16, Ap + aoff + kofs + i * 8);
            cp16(sbm + i * 16, Bp + boff + kofs + i * 8);
        }
    };

    load_chunk(0, 0);
    asm volatile("cp.async.commit_group;" ::: "memory");

    const int lr = (lane & 7) + ((lane >> 3) & 1) * 8;
    const int lc = ((lane >> 4) & 1) * 16;

    for (int c = 0; c < nch; c++) {
        const int s = c & 1;
        if (c + 1 < nch) {
            load_chunk(c + 1, s ^ 1);
            asm volatile("cp.async.commit_group;" ::: "memory");
            asm volatile("cp.async.wait_group 1;" ::: "memory");
        } else {
            asm volatile("cp.async.wait_group 0;" ::: "memory");
        }
        __syncthreads();
        const uint32_t stb = smb + s * STAGE64;

#pragma unroll
        for (int kk = 0; kk < 4; kk++) {
            uint32_t bh[2][4];
#pragma unroll
            for (int h = 0; h < 2; h++) {
                uint32_t bd = stb + PLANE64
                            + (uint32_t)(wn * 32 + h * 16 + lr) * SKB64
                            + kk * 32 + lc;
                ldsm4(bh[h], bd);
            }
#pragma unroll
            for (int mp = 0; mp < 2; mp++) {
                uint32_t ah[2][4];
#pragma unroll
                for (int m2 = 0; m2 < 2; m2++) {
                    uint32_t ad = stb
                        + (uint32_t)(wm * 64 + (mp * 2 + m2) * 16 + lr) * SKB64
                        + kk * 32 + lc;
                    ldsm4(ah[m2], ad);
                }
#pragma unroll
                for (int m2 = 0; m2 < 2; m2++)
#pragma unroll
                    for (int h = 0; h < 2; h++)
#pragma unroll
                        for (int j = 0; j < 2; j++)
                            mma_f16(acc[mp * 2 + m2][h * 2 + j],
                                    ah[m2], bh[h][j], bh[h][j + 2]);
            }
        }
        __syncthreads();
    }

#pragma unroll
    for (int mt = 0; mt < 4; mt++) {
        const int r0 = mtile + wm * 64 + mt * 16 + gq;
#pragma unroll
        for (int nt = 0; nt < 4; nt++) {
            const int col = ntile + wn * 32 + nt * 8 + tg * 2;
            float bx = 0.f, by = 0.f;
            if (bias != nullptr) {
                float2 bb = *(const float2*)(bias + bz * sBias + col);
                bx = bb.x; by = bb.y;
            }
            float o00 = acc[mt][nt][0] + bx;
            float o01 = acc[mt][nt][1] + by;
            float o10 = acc[mt][nt][2] + bx;
            float o11 = acc[mt][nt][3] + by;
            const long i0 = (long)bz * sC + (long)r0 * N + col;
            const long i1 = i0 + (long)8 * N;
            if (F16OUT) {
                __half2 p0, p1;
                p0.x = __float2half_rn(o00); p0.y = __float2half_rn(o01);
                p1.x = __float2half_rn(o10); p1.y = __float2half_rn(o11);
                *(__half2*)(Ch + i0) = p0;
                *(__half2*)(Ch + i1) = p1;
            } else {
                *(float2*)(Cf + i0) = make_float2(o00, o01);
                *(float2*)(Cf + i1) = make_float2(o10, o11);
            }
        }
    }
}

// ---------------------------------------------------------------------------
// sgemm_softmax: fused scores + masked softmax (BK=32 layout, SKB=80).
// W[bz][64 rows][256] = softmax_row( q @ EQ^T + sb - 1e5*mask ) * d^-0.5
// ---------------------------------------------------------------------------
#define SKB 80
#define APL_B (64 * SKB)              // 5120 B
#define BPL_B (256 * SKB)             // 20480 B
#define STG_F (APL_B + BPL_B)         // 25600 B
#define GSMEM_F (2 * STG_F)           // 51200 B
#define BKC 32

__global__ void __launch_bounds__(256, 2) sgemm_softmax(
    const __half* __restrict__ Q,
    const __half* __restrict__ EQEO,
    const float* __restrict__ sb,
    const int* __restrict__ idx,
    __half* __restrict__ Wout)
{
    extern __shared__ char smc[];
    const uint32_t smb = (uint32_t)__cvta_generic_to_shared(smc);
    __shared__ float redm[64][9];
    __shared__ float reds[64][9];

    const int tid  = threadIdx.x;
    const int wid  = tid >> 5;
    const int lane = tid & 31;
    const int gq   = lane >> 2;
    const int tg   = lane & 3;

    const int mtile = blockIdx.y * 64;
    const int bz    = blockIdx.z;
    const int K = D_MODEL, ldb = 2048;

    const __half* A = Q    + (long)bz * LQ * D_MODEL;
    const __half* B = EQEO + (long)bz * NBE * 2048;

    float acc[4][4][4];
#pragma unroll
    for (int i = 0; i < 4; i++)
#pragma unroll
        for (int j = 0; j < 4; j++)
#pragma unroll
            for (int q = 0; q < 4; q++) acc[i][j][q] = 0.f;

    const int lrow = tid >> 2;
    const int lseg = tid & 3;
    const long aoff = (long)(mtile + lrow) * K + lseg * 8;
    const long boff = (long)lrow * ldb + lseg * 8;
    const uint32_t sdst = lrow * SKB + lseg * 16;
    const uint32_t s64 = 64 * SKB;

    auto load_chunk = [&](int c, int s) {
        const long kofs = (long)c * BKC;
        const uint32_t sbs = smb + s * STG_F + sdst;
        cp16(sbs, A + aoff + kofs);
        const uint32_t bb = sbs + APL_B;
        cp16(bb,           B + boff + kofs);
        cp16(bb + s64,     B + boff + (long)64  * ldb + kofs);
        cp16(bb + 2 * s64, B + boff + (long)128 * ldb + kofs);
        cp16(bb + 3 * s64, B + boff + (long)192 * ldb + kofs);
    };

    load_chunk(0, 0);
    asm volatile("cp.async.commit_group;" ::: "memory");

    const int lr = (lane & 7) + ((lane >> 3) & 1) * 8;
    const int lc = ((lane >> 4) & 1) * 16;
    const int nch = K >> 5;

    for (int c = 0; c < nch; c++) {
        const int s = c & 1;
        if (c + 1 < nch) {
            load_chunk(c + 1, s ^ 1);
            asm volatile("cp.async.commit_group;" ::: "memory");
            asm volatile("cp.async.wait_group 1;" ::: "memory");
        } else {
            asm volatile("cp.async.wait_group 0;" ::: "memory");
        }
        __syncthreads();
        const uint32_t stb = smb + s * STG_F;

#pragma unroll
        for (int kk = 0; kk < 2; kk++) {
            uint32_t bh[2][4];
#pragma unroll
            for (int h = 0; h < 2; h++) {
                uint32_t bd = stb + APL_B
                            + (uint32_t)(wid * 32 + h * 16 + lr) * SKB + kk * 32 + lc;
                ldsm4(bh[h], bd);
            }
#pragma unroll
            for (int mp = 0; mp < 2; mp++) {
                uint32_t ah[2][4];
#pragma unroll
                for (int m2 = 0; m2 < 2; m2++) {
                    uint32_t ad = stb
                        + (uint32_t)((mp * 2 + m2) * 16 + lr) * SKB + kk * 32 + lc;
                    ldsm4(ah[m2], ad);
                }
#pragma unroll
                for (int m2 = 0; m2 < 2; m2++)
#pragma unroll
                    for (int h = 0; h < 2; h++)
#pragma unroll
                        for (int j = 0; j < 2; j++)
                            mma_f16(acc[mp * 2 + m2][h * 2 + j],
                                    ah[m2], bh[h][j], bh[h][j + 2]);
            }
        }
        __syncthreads();
    }

    // ---- fused masked softmax epilogue ----
    const float* sbb = sb + bz * NBE;
    const int*  idxb = idx + bz * NBE;

#pragma unroll
    for (int nt = 0; nt < 4; nt++) {
        const int col = wid * 32 + nt * 8 + tg * 2;
        float2 bb = *(const float2*)(sbb + col);
        bool m0 = idxb[col] < 0;
        bool m1 = idxb[col + 1] < 0;
#pragma unroll
        for (int mt = 0; mt < 4; mt++) {
            acc[mt][nt][0] = m0 ? -100000.f : acc[mt][nt][0] + bb.x;
            acc[mt][nt][1] = m1 ? -100000.f : acc[mt][nt][1] + bb.y;
            acc[mt][nt][2] = m0 ? -100000.f : acc[mt][nt][2] + bb.x;
            acc[mt][nt][3] = m1 ? -100000.f : acc[mt][nt][3] + bb.y;
        }
    }

#pragma unroll
    for (int mt = 0; mt < 4; mt++)
#pragma unroll
        for (int rh = 0; rh < 2; rh++) {
            float m = -3.4e38f;
#pragma unroll
            for (int nt = 0; nt < 4; nt++) {
                m = fmaxf(m, acc[mt][nt][rh * 2]);
                m = fmaxf(m, acc[mt][nt][rh * 2 + 1]);
            }
            m = fmaxf(m, __shfl_xor_sync(0xffffffffu, m, 1));
            m = fmaxf(m, __shfl_xor_sync(0xffffffffu, m, 2));
            if (tg == 0) redm[mt * 16 + rh * 8 + gq][wid] = m;
        }
    __syncthreads();

#pragma unroll
    for (int mt = 0; mt < 4; mt++)
#pragma unroll
        for (int rh = 0; rh < 2; rh++) {
            const int rl = mt * 16 + rh * 8 + gq;
            float mall = redm[rl][0];
#pragma unroll
            for (int w = 1; w < 8; w++) mall = fmaxf(mall, redm[rl][w]);
            float ssum = 0.f;
#pragma unroll
            for (int nt = 0; nt < 4; nt++) {
                float e0 = expf(acc[mt][nt][rh * 2]     - mall);
                float e1 = expf(acc[mt][nt][rh * 2 + 1] - mall);
                acc[mt][nt][rh * 2]     = e0;
                acc[mt][nt][rh * 2 + 1] = e1;
                ssum += e0 + e1;
            }
            ssum += __shfl_xor_sync(0xffffffffu, ssum, 1);
            ssum += __shfl_xor_sync(0xffffffffu, ssum, 2);
            if (tg == 0) reds[rl][wid] = ssum;
        }
    __syncthreads();

#pragma unroll
    for (int mt = 0; mt < 4; mt++)
#pragma unroll
        for (int rh = 0; rh < 2; rh++) {
            const int rl = mt * 16 + rh * 8 + gq;
            float sum = reds[rl][0];
#pragma unroll
            for (int w = 1; w < 8; w++) sum += reds[rl][w];
            const float inv = 0.03125f / sum;
            const long rowoff = (long)(bz * LQ + mtile + rl) * NBE;
#pragma unroll
            for (int nt = 0; nt < 4; nt++) {
                const int col = wid * 32 + nt * 8 + tg * 2;
                __half2 p;
                p.x = __float2half_rn(acc[mt][nt][rh * 2]     * inv);
                p.y = __float2half_rn(acc[mt][nt][rh * 2 + 1] * inv);
                *(__half2*)(Wout + rowoff + col) = p;
            }
        }
}

// ---------------------------------------------------------------------------
// query fp32 -> single fp16 plane (RN)
// ---------------------------------------------------------------------------
__global__ void tohalf(const float* __restrict__ x, __half* __restrict__ h, int n4)
{
    int i = blockIdx.x * blockDim.x + threadIdx.x;
    if (i >= n4) return;
    float4 v = ((const float4*)x)[i];
    __half hh[4];
    hh[0] = __float2half_rn(v.x); hh[1] = __float2half_rn(v.y);
    hh[2] = __float2half_rn(v.z); hh[3] = __float2half_rn(v.w);
    ((uint2*)h)[i] = *(uint2*)hh;
}

// fp32 -> fp16 hi/lo split (WO rows of A12)
__global__ void split_f16(const float* __restrict__ x,
                          __half* __restrict__ h, __half* __restrict__ l, int n4)
{
    int i = blockIdx.x * blockDim.x + threadIdx.x;
    if (i >= n4) return;
    float4 v = ((const float4*)x)[i];
    __half hh[4], ll[4];
    split1h(v.x, hh[0], ll[0]); split1h(v.y, hh[1], ll[1]);
    split1h(v.z, hh[2], ll[2]); split1h(v.w, hh[3], ll[3]);
    ((uint2*)h)[i] = *(uint2*)hh;
    ((uint2*)l)[i] = *(uint2*)ll;
}

// split + transpose (D,D) fp32 -> fp16 planes of W^T  (CLOCK CANARY kernel)
__global__ void split_tr(const float* __restrict__ W,
                         __half* __restrict__ Th, __half* __restrict__ Tl)
{
    __shared__ float t[32][33];
    const int c0 = blockIdx.x * 32;
    const int r0 = blockIdx.y * 32;
    const int tx = threadIdx.x, ty = threadIdx.y;
#pragma unroll
    for (int i = 0; i < 32; i += 8)
        t[ty + i][tx] = W[(long)(r0 + ty + i) * D_MODEL + c0 + tx];
    __syncthreads();
#pragma unroll
    for (int i = 0; i < 32; i += 8) {
        float v = t[tx][ty + i];
        __half h, l;
        split1h(v, h, l);
        const long o = (long)(c0 + ty + i) * D_MODEL + r0 + tx;
        Th[o] = h;  Tl[o] = l;
    }
}

// ---------------------------------------------------------------------------
// prep_vec: b2[0:1024]=bK@WQ, b2[1024:2048]=bK@WO^T, vb[0:1024]=WK^T bQ,
// vb[1024]=bQ.bK.  One block per output element.  (uses hi+lo planes, exact)
// ---------------------------------------------------------------------------
__global__ void prep_vec(const __half* __restrict__ A12h,
                         const __half* __restrict__ A12l,
                         const float* __restrict__ WO,
                         const __half* __restrict__ WKTh,
                         const __half* __restrict__ WKTl,
                         const float* __restrict__ bK,
                         const float* __restrict__ bQ,
                         float* __restrict__ b2, float* __restrict__ vb)
{
    const int n = blockIdx.x;
    const int t = threadIdx.x;
    float s = 0.f;

    if (n < 1024) {
        const uint2 h2 = ((const uint2*)(A12h + (long)n * D_MODEL))[t];
        const uint2 l2 = ((const uint2*)(A12l + (long)n * D_MODEL))[t];
        const __half* hp = (const __half*)&h2;
        const __half* lp = (const __half*)&l2;
        float4 b = ((const float4*)bK)[t];
        s = (__half2float(hp[0]) + __half2float(lp[0])) * b.x
          + (__half2float(hp[1]) + __half2float(lp[1])) * b.y
          + (__half2float(hp[2]) + __half2float(lp[2])) * b.z
          + (__half2float(hp[3]) + __half2float(lp[3])) * b.w;
    } else if (n < 2048) {
        float4 w = ((const float4*)(WO + (long)(n - 1024) * D_MODEL))[t];
        float4 b = ((const float4*)bK)[t];
        s = w.x * b.x + w.y * b.y + w.z * b.z + w.w * b.w;
    } else if (n < 3072) {
        const uint2 h2 = ((const uint2*)(WKTh + (long)(n - 2048) * D_MODEL))[t];
        const uint2 l2 = ((const uint2*)(WKTl + (long)(n - 2048) * D_MODEL))[t];
        const __half* hp = (const __half*)&h2;
        const __half* lp = (const __half*)&l2;
        float4 b = ((const float4*)bQ)[t];
        s = (__half2float(hp[0]) + __half2float(lp[0])) * b.x
          + (__half2float(hp[1]) + __half2float(lp[1])) * b.y
          + (__half2float(hp[2]) + __half2float(lp[2])) * b.z
          + (__half2float(hp[3]) + __half2float(lp[3])) * b.w;
    } else {
        float4 q = ((const float4*)bQ)[t];
        float4 b = ((const float4*)bK)[t];
        s = q.x * b.x + q.y * b.y + q.z * b.z + q.w * b.w;
    }

    __shared__ float red[8];
#pragma unroll
    for (int o = 16; o; o >>= 1) s += __shfl_xor_sync(0xffffffffu, s, o);
    if ((t & 31) == 0) red[t >> 5] = s;
    __syncthreads();
    if (t == 0) {
        float tot = 0.f;
#pragma unroll
        for (int i = 0; i < 8; i++) tot += red[i];
        if (n < 2048)      b2[n] = tot;
        else if (n < 3072) vb[n - 2048] = tot;
        else               vb[1024] = tot;
    }
}

// ---------------------------------------------------------------------------
// gather (single fp16 plane) + score-bias
// ---------------------------------------------------------------------------
__global__ void gather_sb(const float* __restrict__ E,
                          const int* __restrict__ idx,
                          const float* __restrict__ vb,
                          __half* __restrict__ Gh,
                          float* __restrict__ sb)
{
    const int r = blockIdx.x;
    int s = idx[r];
    if (s < 0) s = 0;
    const int i = threadIdx.x;
    float4 v = ((const float4*)(E + (long)s * D_MODEL))[i];
    __half hh[4];
    hh[0] = __float2half_rn(v.x); hh[1] = __float2half_rn(v.y);
    hh[2] = __float2half_rn(v.z); hh[3] = __float2half_rn(v.w);
    ((uint2*)(Gh + (long)r * D_MODEL))[i] = *(uint2*)hh;

    float4 w = ((const float4*)vb)[i];
    float d = v.x * w.x + v.y * w.y + v.z * w.z + v.w * w.w;
    __shared__ float red[8];
#pragma unroll
    for (int o = 16; o; o >>= 1) d += __shfl_xor_sync(0xffffffffu, d, o);
    if ((i & 31) == 0) red[i >> 5] = d;
    __syncthreads();
    if (i == 0) {
        float tot = vb[1024];
#pragma unroll
        for (int k = 0; k < 8; k++) tot += red[k];
        sb[r] = tot;
    }
}

// ---------------------------------------------------------------------------
// per-batch fp16 transpose of the EO half of EQEO -> EOT[b] (D x NBE)
// ---------------------------------------------------------------------------
__global__ void transpose_f16(const __half* __restrict__ EQEO,
                              __half* __restrict__ EOT)
{
    __shared__ __half t[32][34];
    const int b  = blockIdx.z;
    const int c0 = blockIdx.x * 32;
    const int r0 = blockIdx.y * 32;
    const int tx = threadIdx.x, ty = threadIdx.y;
#pragma unroll
    for (int i = 0; i < 32; i += 8)
        t[ty + i][tx] = EQEO[(long)(b * NBE + r0 + ty + i) * 2048 + 1024 + c0 + tx];
    __syncthreads();
#pragma unroll
    for (int i = 0; i < 32; i += 8)
        EOT[(long)b * NBE * D_MODEL + (long)(c0 + ty + i) * NBE + r0 + tx]
            = t[tx][ty + i];
}

// ---------------------------------------------------------------------------
// Row LayerNorm over D=1024 (biased var, eps=1e-5).
// ---------------------------------------------------------------------------
__global__ void layernorm_k(const float* __restrict__ X,
                            const float* __restrict__ g,
                            const float* __restrict__ b,
                            float* __restrict__ O)
{
    const int row = blockIdx.x;
    const int t   = threadIdx.x;
    const float* x = X + (long)row * D_MODEL;

    float4 v = *(const float4*)(x + t * 4);
    float s  = v.x + v.y + v.z + v.w;
    float sq = v.x * v.x + v.y * v.y + v.z * v.z + v.w * v.w;

    __shared__ float rs[8], rq[8];
#pragma unroll
    for (int o = 16; o; o >>= 1) {
        s  += __shfl_xor_sync(0xffffffffu, s,  o);
        sq += __shfl_xor_sync(0xffffffffu, sq, o);
    }
    if ((t & 31) == 0) { rs[t >> 5] = s; rq[t >> 5] = sq; }
    __syncthreads();
    float S = 0.f, Q = 0.f;
#pragma unroll
    for (int i = 0; i < 8; i++) { S += rs[i]; Q += rq[i]; }

    float mu  = S * (1.f / 1024.f);
    float var = Q * (1.f / 1024.f) - mu * mu;
    float inv = rsqrtf(var + 1e-5f);

    float4 gg = *(const float4*)(g + t * 4);
    float4 bb = *(const float4*)(b + t * 4);
    float4 o;
    o.x = (v.x - mu) * inv * gg.x + bb.x;
    o.y = (v.y - mu) * inv * gg.y + bb.y;
    o.z = (v.z - mu) * inv * gg.z + bb.z;
    o.w = (v.w - mu) * inv * gg.w + bb.w;
    *(float4*)(O + (long)row * D_MODEL + t * 4) = o;
}

// ---------------------------------------------------------------------------
extern "C" void kernel_launch(void* const* d_in, const int* in_sizes, int n_in,
                              void* d_out, int out_size)
{
    const float* query   = (const float*)d_in[0];
    const float* ent_emb = (const float*)d_in[1];
    const int*   idx     = (const int*)  d_in[2];
    const float* WQ_w = (const float*)d_in[4];
    const float* WQ_b = (const float*)d_in[5];
    const float* WK_w = (const float*)d_in[6];
    const float* WK_b = (const float*)d_in[7];
    const float* WO_w = (const float*)d_in[8];
    const float* WO_b = (const float*)d_in[9];
    const float* ln_g = (const float*)d_in[10];
    const float* ln_b = (const float*)d_in[11];
    float* out = (float*)d_out;

    __half *qh, *A12h, *A12l, *WKTh, *WKTl, *Gh, *T12, *EQEO, *EOT, *Wh;
    float *sb, *vb, *b2, *P;
    cudaGetSymbolAddress((void**)&qh,   g_qh);
    cudaGetSymbolAddress((void**)&A12h, g_A12h); cudaGetSymbolAddress((void**)&A12l, g_A12l);
    cudaGetSymbolAddress((void**)&WKTh, g_WKTh); cudaGetSymbolAddress((void**)&WKTl, g_WKTl);
    cudaGetSymbolAddress((void**)&Gh,   g_Gh);
    cudaGetSymbolAddress((void**)&T12,  g_T12);
    cudaGetSymbolAddress((void**)&EQEO, g_EQEO);
    cudaGetSymbolAddress((void**)&EOT,  g_EOT);
    cudaGetSymbolAddress((void**)&Wh,   g_Wh);
    cudaGetSymbolAddress((void**)&sb,   g_sb);
    cudaGetSymbolAddress((void**)&vb,   g_vb);
    cudaGetSymbolAddress((void**)&b2,   g_b2);
    cudaGetSymbolAddress((void**)&P,    g_P);

    cudaFuncSetAttribute((const void*)gemm2<true >,
        cudaFuncAttributeMaxDynamicSharedMemorySize, GSMEM64);
    cudaFuncSetAttribute((const void*)gemm2<false>,
        cudaFuncAttributeMaxDynamicSharedMemorySize, GSMEM64);
    cudaFuncSetAttribute((const void*)sgemm_softmax,
        cudaFuncAttributeMaxDynamicSharedMemorySize, GSMEM_F);

    const int DD4 = D_MODEL * D_MODEL / 4;
    const long DD = (long)D_MODEL * D_MODEL;

    // 0. input preprocessing
    tohalf<<<(ML * D_MODEL / 4 + 255) / 256, 256>>>(query, qh, ML * D_MODEL / 4);
    split_tr<<<dim3(32, 32), dim3(32, 8)>>>(WQ_w, A12h, A12l);
    split_f16<<<(DD4 + 255) / 256, 256>>>(WO_w, A12h + DD, A12l + DD, DD4);
    split_tr<<<dim3(32, 32), dim3(32, 8)>>>(WK_w, WKTh, WKTl);
    prep_vec<<<3073, 256>>>(A12h, A12l, WO_w, WKTh, WKTl, WK_b, WQ_b, b2, vb);
    gather_sb<<<MB, 256>>>(ent_emb, idx, vb, Gh, sb);

    // 1. merged weight product: [T1;T2] = [WQ^T;WO] @ WK  (1-term, BK=64)
    gemm2<true><<<dim3(8, 16, 1), 256, GSMEM64>>>(
        A12h, 0, WKTh, 0, D_MODEL, nullptr, T12, 0,
        D_MODEL, D_MODEL, nullptr, 0);

    // 2. EQEO = G @ [T1;T2]^T + bias2   [4096 x 2048 x 1024]
    gemm2<true><<<dim3(16, 32, 1), 256, GSMEM64>>>(
        Gh, 0, T12, 0, D_MODEL, nullptr, EQEO, 0,
        2048, D_MODEL, b2, 0);

    // 3. fused scores + masked softmax -> fp16 weights
    sgemm_softmax<<<dim3(1, 16, BATCH), 256, GSMEM_F>>>(
        qh, EQEO, sb, idx, Wh);

    // 4. EOT[b] = EO[b]^T
    transpose_f16<<<dim3(32, 8, BATCH), dim3(32, 8)>>>(EQEO, EOT);

    // 5. P[b] = W[b] @ EOT[b]^T + bO   [16 x (1024 x 1024 x 256)], K=256
    gemm2<false><<<dim3(8, 8, BATCH), 256, GSMEM64>>>(
        Wh, (long)LQ * NBE, EOT, (long)D_MODEL * NBE, NBE,
        P, nullptr, (long)LQ * D_MODEL, D_MODEL, NBE, WO_b, 0);

    // 6. LayerNorm -> out
    layernorm_k<<<ML, 256>>>(P, ln_g, ln_b, out);
}

// round 14
// speedup vs baseline: 1.0930x; 1.0930x over previous
#include <cuda_runtime.h>
#include <cuda_bf16.h>
#include <cuda_fp16.h>
#include <cstdint>

// ---------------------------------------------------------------------------
// Problem constants
// ---------------------------------------------------------------------------
#define D_MODEL 1024
#define BATCH   16
#define LQ      1024
#define NBE     256
#define ML (BATCH * LQ)    // 16384
#define MB (BATCH * NBE)   // 4096

// ---------------------------------------------------------------------------
// Scratch (__device__ globals; no allocation anywhere)
// ---------------------------------------------------------------------------
__device__ __half  g_qh  [ML * D_MODEL];                 // query fp16 (1 plane)
__device__ __half  g_A12h[2048 * D_MODEL];               // [WQ^T ; WO] hi plane
__device__ __half  g_A12l[2048 * D_MODEL];               // lo plane (bias vectors only)
__device__ __half  g_WKTh[D_MODEL * D_MODEL];            // WK^T hi
__device__ __half  g_WKTl[D_MODEL * D_MODEL];            // WK^T lo (bias vectors only)
__device__ __half  g_Gh  [MB * D_MODEL];                 // gathered ents (1 plane)
__device__ __half  g_T12 [2048 * D_MODEL];               // [T1; T2] fp16
__device__ __half  g_EQEO[MB * 2048];                    // [EQ | EO] fp16
__device__ __half  g_EOT [MB * D_MODEL];                 // EO^T per batch
__device__ float   g_sb  [MB];                           // bQ.ENT score bias
__device__ float   g_vb  [1025];                         // WK^T bQ, [1024]=bQ.bK
__device__ float   g_b2  [2048];                         // [bK@WQ | bK@WO^T]
__device__ __half  g_Wh  [ML * NBE];                     // softmax wts fp16 (1 plane)
__device__ float   g_P   [ML * D_MODEL];                 // pre-LN fp32

// ---------------------------------------------------------------------------
// Helpers
// ---------------------------------------------------------------------------
__device__ __forceinline__ void split1h(float x, __half& h, __half& l) {
    h = __float2half_rn(x);
    l = __float2half_rn(x - __half2float(h));
}

__device__ __forceinline__ void cp16(uint32_t dst, const void* src) {
    asm volatile("cp.async.cg.shared.global [%0], [%1], 16;"
                 :: "r"(dst), "l"(src) : "memory");
}
__device__ __forceinline__ void ldsm4(uint32_t* r, uint32_t addr) {
    asm volatile("ldmatrix.sync.aligned.m8n8.x4.shared.b16 {%0,%1,%2,%3}, [%4];"
                 : "=r"(r[0]), "=r"(r[1]), "=r"(r[2]), "=r"(r[3]) : "r"(addr));
}
__device__ __forceinline__ void mma_f16(float* c, const uint32_t* a,
                                        uint32_t b0, uint32_t b1) {
    asm volatile(
        "mma.sync.aligned.m16n8k16.row.col.f32.f16.f16.f32 "
        "{%0,%1,%2,%3}, {%4,%5,%6,%7}, {%8,%9}, {%0,%1,%2,%3};"
        : "+f"(c[0]), "+f"(c[1]), "+f"(c[2]), "+f"(c[3])
        : "r"(a[0]), "r"(a[1]), "r"(a[2]), "r"(a[3]), "r"(b0), "r"(b1));
}

#define BKC 32
#define SKB 80                        // smem row stride bytes (40 halves)
#define PLANE_B (128 * SKB)           // 10240 B per plane per stage

// ---------------------------------------------------------------------------
// gemm2: fp16 NT GEMM (1-term): C[bz][M,N] = A @ B^T (+bias)
// A fp16 plane (lda=K), B fp16 plane (row stride ldb).
// Output fp16 (F16OUT) or fp32.  bias[bz*sBias + col].
// CTA 128x128, BK=32, 8 warps (2x4, warp tile 64x32),
// 2-stage cp.async pipeline, 256 threads, 2 CTAs/SM.
// ---------------------------------------------------------------------------
#define STAGE_B (2 * PLANE_B)         // A + B
#define GSMEM_G (2 * STAGE_B)         // 40960 B

template<bool F16OUT>
__global__ void __launch_bounds__(256, 2) gemm2(
    const __half* __restrict__ Ap, long sA,
    const __half* __restrict__ Bp, long sB, int ldb,
    float* __restrict__ Cf, __half* __restrict__ Ch, long sC,
    int N, int K,
    const float* __restrict__ bias, long sBias)
{
    extern __shared__ char smc[];
    const uint32_t smb = (uint32_t)__cvta_generic_to_shared(smc);

    const int tid  = threadIdx.x;
    const int wid  = tid >> 5;
    const int lane = tid & 31;
    const int wm   = wid >> 2;
    const int wn   = wid & 3;
    const int gq   = lane >> 2;
    const int tg   = lane & 3;

    const int mtile = blockIdx.y * 128;
    const int ntile = blockIdx.x * 128;
    const int bz    = blockIdx.z;
    Ap += (long)bz * sA;
    Bp += (long)bz * sB;

    const int nch = K >> 5;

    float acc[4][4][4];
#pragma unroll
    for (int i = 0; i < 4; i++)
#pragma unroll
        for (int j = 0; j < 4; j++)
#pragma unroll
            for (int q = 0; q < 4; q++) acc[i][j][q] = 0.f;

    const int lrow = tid >> 2;
    const int lseg = tid & 3;
    const long aoff = (long)(mtile + lrow) * K + lseg * 8;
    const long boff = (long)(ntile + lrow) * ldb + lseg * 8;
    const long ahalf = (long)64 * K;
    const long bhalf = (long)64 * ldb;
    const uint32_t sdst = lrow * SKB + lseg * 16;
    const uint32_t shalf = 64 * SKB;

    auto load_chunk = [&](int c, int s) {
        const long kofs = (long)c * BKC;
        const uint32_t sb = smb + s * STAGE_B + sdst;
        cp16(sb,                     Ap + aoff + kofs);
        cp16(sb + shalf,             Ap + aoff + ahalf + kofs);
        cp16(sb + PLANE_B,           Bp + boff + kofs);
        cp16(sb + PLANE_B + shalf,   Bp + boff + bhalf + kofs);
    };

    load_chunk(0, 0);
    asm volatile("cp.async.commit_group;" ::: "memory");

    const int lr = (lane & 7) + ((lane >> 3) & 1) * 8;
    const int lc = ((lane >> 4) & 1) * 16;

    for (int c = 0; c < nch; c++) {
        const int s = c & 1;
        if (c + 1 < nch) {
            load_chunk(c + 1, s ^ 1);
            asm volatile("cp.async.commit_group;" ::: "memory");
            asm volatile("cp.async.wait_group 1;" ::: "memory");
        } else {
            asm volatile("cp.async.wait_group 0;" ::: "memory");
        }
        __syncthreads();
        const uint32_t stb = smb + s * STAGE_B;

#pragma unroll
        for (int kk = 0; kk < 2; kk++) {
            uint32_t bh[2][4];
#pragma unroll
            for (int h = 0; h < 2; h++) {
                uint32_t bd = stb + PLANE_B
                            + (uint32_t)(wn * 32 + h * 16 + lr) * SKB + kk * 32 + lc;
                ldsm4(bh[h], bd);
            }
#pragma unroll
            for (int mp = 0; mp < 2; mp++) {
                uint32_t ah[2][4];
#pragma unroll
                for (int m2 = 0; m2 < 2; m2++) {
                    uint32_t ad = stb
                        + (uint32_t)(wm * 64 + (mp * 2 + m2) * 16 + lr) * SKB
                        + kk * 32 + lc;
                    ldsm4(ah[m2], ad);
                }
#pragma unroll
                for (int m2 = 0; m2 < 2; m2++)
#pragma unroll
                    for (int h = 0; h < 2; h++)
#pragma unroll
                        for (int j = 0; j < 2; j++)
                            mma_f16(acc[mp * 2 + m2][h * 2 + j],
                                    ah[m2], bh[h][j], bh[h][j + 2]);
            }
        }
        __syncthreads();
    }

#pragma unroll
    for (int mt = 0; mt < 4; mt++) {
        const int r0 = mtile + wm * 64 + mt * 16 + gq;
#pragma unroll
        for (int nt = 0; nt < 4; nt++) {
            const int col = ntile + wn * 32 + nt * 8 + tg * 2;
            float bx = 0.f, by = 0.f;
            if (bias != nullptr) {
                float2 bb = *(const float2*)(bias + bz * sBias + col);
                bx = bb.x; by = bb.y;
            }
            float o00 = acc[mt][nt][0] + bx;
            float o01 = acc[mt][nt][1] + by;
            float o10 = acc[mt][nt][2] + bx;
            float o11 = acc[mt][nt][3] + by;
            const long i0 = (long)bz * sC + (long)r0 * N + col;
            const long i1 = i0 + (long)8 * N;
            if (F16OUT) {
                __half2 p0, p1;
                p0.x = __float2half_rn(o00); p0.y = __float2half_rn(o01);
                p1.x = __float2half_rn(o10); p1.y = __float2half_rn(o11);
                *(__half2*)(Ch + i0) = p0;
                *(__half2*)(Ch + i1) = p1;
            } else {
                *(float2*)(Cf + i0) = make_float2(o00, o01);
                *(float2*)(Cf + i1) = make_float2(o10, o11);
            }
        }
    }
}

// ---------------------------------------------------------------------------
// sgemm_softmax: fused scores + masked softmax (BK=32, SKB=80).
// W[bz][64 rows][256] = softmax_row( q @ EQ^T + sb - 1e5*mask ) * d^-0.5
// ---------------------------------------------------------------------------
#define APL_B (64 * SKB)              // 5120 B
#define BPL_B (256 * SKB)             // 20480 B
#define STG_F (APL_B + BPL_B)         // 25600 B
#define GSMEM_F (2 * STG_F)           // 51200 B

__global__ void __launch_bounds__(256, 2) sgemm_softmax(
    const __half* __restrict__ Q,
    const __half* __restrict__ EQEO,
    const float* __restrict__ sb,
    const int* __restrict__ idx,
    __half* __restrict__ Wout)
{
    extern __shared__ char smc[];
    const uint32_t smb = (uint32_t)__cvta_generic_to_shared(smc);
    __shared__ float redm[64][9];
    __shared__ float reds[64][9];

    const int tid  = threadIdx.x;
    const int wid  = tid >> 5;
    const int lane = tid & 31;
    const int gq   = lane >> 2;
    const int tg   = lane & 3;

    const int mtile = blockIdx.y * 64;
    const int bz    = blockIdx.z;
    const int K = D_MODEL, ldb = 2048;

    const __half* A = Q    + (long)bz * LQ * D_MODEL;
    const __half* B = EQEO + (long)bz * NBE * 2048;

    float acc[4][4][4];
#pragma unroll
    for (int i = 0; i < 4; i++)
#pragma unroll
        for (int j = 0; j < 4; j++)
#pragma unroll
            for (int q = 0; q < 4; q++) acc[i][j][q] = 0.f;

    const int lrow = tid >> 2;
    const int lseg = tid & 3;
    const long aoff = (long)(mtile + lrow) * K + lseg * 8;
    const long boff = (long)lrow * ldb + lseg * 8;
    const uint32_t sdst = lrow * SKB + lseg * 16;
    const uint32_t s64 = 64 * SKB;

    auto load_chunk = [&](int c, int s) {
        const long kofs = (long)c * BKC;
        const uint32_t sbs = smb + s * STG_F + sdst;
        cp16(sbs, A + aoff + kofs);
        const uint32_t bb = sbs + APL_B;
        cp16(bb,           B + boff + kofs);
        cp16(bb + s64,     B + boff + (long)64  * ldb + kofs);
        cp16(bb + 2 * s64, B + boff + (long)128 * ldb + kofs);
        cp16(bb + 3 * s64, B + boff + (long)192 * ldb + kofs);
    };

    load_chunk(0, 0);
    asm volatile("cp.async.commit_group;" ::: "memory");

    const int lr = (lane & 7) + ((lane >> 3) & 1) * 8;
    const int lc = ((lane >> 4) & 1) * 16;
    const int nch = K >> 5;

    for (int c = 0; c < nch; c++) {
        const int s = c & 1;
        if (c + 1 < nch) {
            load_chunk(c + 1, s ^ 1);
            asm volatile("cp.async.commit_group;" ::: "memory");
            asm volatile("cp.async.wait_group 1;" ::: "memory");
        } else {
            asm volatile("cp.async.wait_group 0;" ::: "memory");
        }
        __syncthreads();
        const uint32_t stb = smb + s * STG_F;

#pragma unroll
        for (int kk = 0; kk < 2; kk++) {
            uint32_t bh[2][4];
#pragma unroll
            for (int h = 0; h < 2; h++) {
                uint32_t bd = stb + APL_B
                            + (uint32_t)(wid * 32 + h * 16 + lr) * SKB + kk * 32 + lc;
                ldsm4(bh[h], bd);
            }
#pragma unroll
            for (int mp = 0; mp < 2; mp++) {
                uint32_t ah[2][4];
#pragma unroll
                for (int m2 = 0; m2 < 2; m2++) {
                    uint32_t ad = stb
                        + (uint32_t)((mp * 2 + m2) * 16 + lr) * SKB + kk * 32 + lc;
                    ldsm4(ah[m2], ad);
                }
#pragma unroll
                for (int m2 = 0; m2 < 2; m2++)
#pragma unroll
                    for (int h = 0; h < 2; h++)
#pragma unroll
                        for (int j = 0; j < 2; j++)
                            mma_f16(acc[mp * 2 + m2][h * 2 + j],
                                    ah[m2], bh[h][j], bh[h][j + 2]);
            }
        }
        __syncthreads();
    }

    // ---- fused masked softmax epilogue ----
    const float* sbb = sb + bz * NBE;
    const int*  idxb = idx + bz * NBE;

#pragma unroll
    for (int nt = 0; nt < 4; nt++) {
        const int col = wid * 32 + nt * 8 + tg * 2;
        float2 bb = *(const float2*)(sbb + col);
        bool m0 = idxb[col] < 0;
        bool m1 = idxb[col + 1] < 0;
#pragma unroll
        for (int mt = 0; mt < 4; mt++) {
            acc[mt][nt][0] = m0 ? -100000.f : acc[mt][nt][0] + bb.x;
            acc[mt][nt][1] = m1 ? -100000.f : acc[mt][nt][1] + bb.y;
            acc[mt][nt][2] = m0 ? -100000.f : acc[mt][nt][2] + bb.x;
            acc[mt][nt][3] = m1 ? -100000.f : acc[mt][nt][3] + bb.y;
        }
    }

#pragma unroll
    for (int mt = 0; mt < 4; mt++)
#pragma unroll
        for (int rh = 0; rh < 2; rh++) {
            float m = -3.4e38f;
#pragma unroll
            for (int nt = 0; nt < 4; nt++) {
                m = fmaxf(m, acc[mt][nt][rh * 2]);
                m = fmaxf(m, acc[mt][nt][rh * 2 + 1]);
            }
            m = fmaxf(m, __shfl_xor_sync(0xffffffffu, m, 1));
            m = fmaxf(m, __shfl_xor_sync(0xffffffffu, m, 2));
            if (tg == 0) redm[mt * 16 + rh * 8 + gq][wid] = m;
        }
    __syncthreads();

#pragma unroll
    for (int mt = 0; mt < 4; mt++)
#pragma unroll
        for (int rh = 0; rh < 2; rh++) {
            const int rl = mt * 16 + rh * 8 + gq;
            float mall = redm[rl][0];
#pragma unroll
            for (int w = 1; w < 8; w++) mall = fmaxf(mall, redm[rl][w]);
            float ssum = 0.f;
#pragma unroll
            for (int nt = 0; nt < 4; nt++) {
                float e0 = expf(acc[mt][nt][rh * 2]     - mall);
                float e1 = expf(acc[mt][nt][rh * 2 + 1] - mall);
                acc[mt][nt][rh * 2]     = e0;
                acc[mt][nt][rh * 2 + 1] = e1;
                ssum += e0 + e1;
            }
            ssum += __shfl_xor_sync(0xffffffffu, ssum, 1);
            ssum += __shfl_xor_sync(0xffffffffu, ssum, 2);
            if (tg == 0) reds[rl][wid] = ssum;
        }
    __syncthreads();

#pragma unroll
    for (int mt = 0; mt < 4; mt++)
#pragma unroll
        for (int rh = 0; rh < 2; rh++) {
            const int rl = mt * 16 + rh * 8 + gq;
            float sum = reds[rl][0];
#pragma unroll
            for (int w = 1; w < 8; w++) sum += reds[rl][w];
            const float inv = 0.03125f / sum;
            const long rowoff = (long)(bz * LQ + mtile + rl) * NBE;
#pragma unroll
            for (int nt = 0; nt < 4; nt++) {
                const int col = wid * 32 + nt * 8 + tg * 2;
                __half2 p;
                p.x = __float2half_rn(acc[mt][nt][rh * 2]     * inv);
                p.y = __float2half_rn(acc[mt][nt][rh * 2 + 1] * inv);
                *(__half2*)(Wout + rowoff + col) = p;
            }
        }
}

// ---------------------------------------------------------------------------
// query fp32 -> single fp16 plane (RN)
// ---------------------------------------------------------------------------
__global__ void tohalf(const float* __restrict__ x, __half* __restrict__ h, int n4)
{
    int i = blockIdx.x * blockDim.x + threadIdx.x;
    if (i >= n4) return;
    float4 v = ((const float4*)x)[i];
    __half hh[4];
    hh[0] = __float2half_rn(v.x); hh[1] = __float2half_rn(v.y);
    hh[2] = __float2half_rn(v.z); hh[3] = __float2half_rn(v.w);
    ((uint2*)h)[i] = *(uint2*)hh;
}

// fp32 -> fp16 hi/lo split (WO rows of A12)
__global__ void split_f16(const float* __restrict__ x,
                          __half* __restrict__ h, __half* __restrict__ l, int n4)
{
    int i = blockIdx.x * blockDim.x + threadIdx.x;
    if (i >= n4) return;
    float4 v = ((const float4*)x)[i];
    __half hh[4], ll[4];
    split1h(v.x, hh[0], ll[0]); split1h(v.y, hh[1], ll[1]);
    split1h(v.z, hh[2], ll[2]); split1h(v.w, hh[3], ll[3]);
    ((uint2*)h)[i] = *(uint2*)hh;
    ((uint2*)l)[i] = *(uint2*)ll;
}

// split + transpose (D,D) fp32 -> fp16 planes of W^T  (CLOCK CANARY kernel)
__global__ void split_tr(const float* __restrict__ W,
                         __half* __restrict__ Th, __half* __restrict__ Tl)
{
    __shared__ float t[32][33];
    const int c0 = blockIdx.x * 32;
    const int r0 = blockIdx.y * 32;
    const int tx = threadIdx.x, ty = threadIdx.y;
#pragma unroll
    for (int i = 0; i < 32; i += 8)
        t[ty + i][tx] = W[(long)(r0 + ty + i) * D_MODEL + c0 + tx];
    __syncthreads();
#pragma unroll
    for (int i = 0; i < 32; i += 8) {
        float v = t[tx][ty + i];
        __half h, l;
        split1h(v, h, l);
        const long o = (long)(c0 + ty + i) * D_MODEL + r0 + tx;
        Th[o] = h;  Tl[o] = l;
    }
}

// ---------------------------------------------------------------------------
// prep_vec: b2[0:1024]=bK@WQ, b2[1024:2048]=bK@WO^T, vb[0:1024]=WK^T bQ,
// vb[1024]=bQ.bK.  One block per output element.  (hi+lo planes, exact)
// ---------------------------------------------------------------------------
__global__ void prep_vec(const __half* __restrict__ A12h,
                         const __half* __restrict__ A12l,
                         const float* __restrict__ WO,
                         const __half* __restrict__ WKTh,
                         const __half* __restrict__ WKTl,
                         const float* __restrict__ bK,
                         const float* __restrict__ bQ,
                         float* __restrict__ b2, float* __restrict__ vb)
{
    const int n = blockIdx.x;
    const int t = threadIdx.x;
    float s = 0.f;

    if (n < 1024) {
        const uint2 h2 = ((const uint2*)(A12h + (long)n * D_MODEL))[t];
        const uint2 l2 = ((const uint2*)(A12l + (long)n * D_MODEL))[t];
        const __half* hp = (const __half*)&h2;
        const __half* lp = (const __half*)&l2;
        float4 b = ((const float4*)bK)[t];
        s = (__half2float(hp[0]) + __half2float(lp[0])) * b.x
          + (__half2float(hp[1]) + __half2float(lp[1])) * b.y
          + (__half2float(hp[2]) + __half2float(lp[2])) * b.z
          + (__half2float(hp[3]) + __half2float(lp[3])) * b.w;
    } else if (n < 2048) {
        float4 w = ((const float4*)(WO + (long)(n - 1024) * D_MODEL))[t];
        float4 b = ((const float4*)bK)[t];
        s = w.x * b.x + w.y * b.y + w.z * b.z + w.w * b.w;
    } else if (n < 3072) {
        const uint2 h2 = ((const uint2*)(WKTh + (long)(n - 2048) * D_MODEL))[t];
        const uint2 l2 = ((const uint2*)(WKTl + (long)(n - 2048) * D_MODEL))[t];
        const __half* hp = (const __half*)&h2;
        const __half* lp = (const __half*)&l2;
        float4 b = ((const float4*)bQ)[t];
        s = (__half2float(hp[0]) + __half2float(lp[0])) * b.x
          + (__half2float(hp[1]) + __half2float(lp[1])) * b.y
          + (__half2float(hp[2]) + __half2float(lp[2])) * b.z
          + (__half2float(hp[3]) + __half2float(lp[3])) * b.w;
    } else {
        float4 q = ((const float4*)bQ)[t];
        float4 b = ((const float4*)bK)[t];
        s = q.x * b.x + q.y * b.y + q.z * b.z + q.w * b.w;
    }

    __shared__ float red[8];
#pragma unroll
    for (int o = 16; o; o >>= 1) s += __shfl_xor_sync(0xffffffffu, s, o);
    if ((t & 31) == 0) red[t >> 5] = s;
    __syncthreads();
    if (t == 0) {
        float tot = 0.f;
#pragma unroll
        for (int i = 0; i < 8; i++) tot += red[i];
        if (n < 2048)      b2[n] = tot;
        else if (n < 3072) vb[n - 2048] = tot;
        else               vb[1024] = tot;
    }
}

// ---------------------------------------------------------------------------
// gather (single fp16 plane) + score-bias
// ---------------------------------------------------------------------------
__global__ void gather_sb(const float* __restrict__ E,
                          const int* __restrict__ idx,
                          const float* __restrict__ vb,
                          __half* __restrict__ Gh,
                          float* __restrict__ sb)
{
    const int r = blockIdx.x;
    int s = idx[r];
    if (s < 0) s = 0;
    const int i = threadIdx.x;
    float4 v = ((const float4*)(E + (long)s * D_MODEL))[i];
    __half hh[4];
    hh[0] = __float2half_rn(v.x); hh[1] = __float2half_rn(v.y);
    hh[2] = __float2half_rn(v.z); hh[3] = __float2half_rn(v.w);
    ((uint2*)(Gh + (long)r * D_MODEL))[i] = *(uint2*)hh;

    float4 w = ((const float4*)vb)[i];
    float d = v.x * w.x + v.y * w.y + v.z * w.z + v.w * w.w;
    __shared__ float red[8];
#pragma unroll
    for (int o = 16; o; o >>= 1) d += __shfl_xor_sync(0xffffffffu, d, o);
    if ((i & 31) == 0) red[i >> 5] = d;
    __syncthreads();
    if (i == 0) {
        float tot = vb[1024];
#pragma unroll
        for (int k = 0; k < 8; k++) tot += red[k];
        sb[r] = tot;
    }
}

// ---------------------------------------------------------------------------
// per-batch fp16 transpose of the EO half of EQEO -> EOT[b] (D x NBE)
// ---------------------------------------------------------------------------
__global__ void transpose_f16(const __half* __restrict__ EQEO,
                              __half* __restrict__ EOT)
{
    __shared__ __half t[32][34];
    const int b  = blockIdx.z;
    const int c0 = blockIdx.x * 32;
    const int r0 = blockIdx.y * 32;
    const int tx = threadIdx.x, ty = threadIdx.y;
#pragma unroll
    for (int i = 0; i < 32; i += 8)
        t[ty + i][tx] = EQEO[(long)(b * NBE + r0 + ty + i) * 2048 + 1024 + c0 + tx];
    __syncthreads();
#pragma unroll
    for (int i = 0; i < 32; i += 8)
        EOT[(long)b * NBE * D_MODEL + (long)(c0 + ty + i) * NBE + r0 + tx]
            = t[tx][ty + i];
}

// ---------------------------------------------------------------------------
// Row LayerNorm over D=1024 (biased var, eps=1e-5).
// ---------------------------------------------------------------------------
__global__ void layernorm_k(const float* __restrict__ X,
                            const float* __restrict__ g,
                            const float* __restrict__ b,
                            float* __restrict__ O)
{
    const int row = blockIdx.x;
    const int t   = threadIdx.x;
    const float* x = X + (long)row * D_MODEL;

    float4 v = *(const float4*)(x + t * 4);
    float s  = v.x + v.y + v.z + v.w;
    float sq = v.x * v.x + v.y * v.y + v.z * v.z + v.w * v.w;

    __shared__ float rs[8], rq[8];
#pragma unroll
    for (int o = 16; o; o >>= 1) {
        s  += __shfl_xor_sync(0xffffffffu, s,  o);
        sq += __shfl_xor_sync(0xffffffffu, sq, o);
    }
    if ((t & 31) == 0) { rs[t >> 5] = s; rq[t >> 5] = sq; }
    __syncthreads();
    float S = 0.f, Q = 0.f;
#pragma unroll
    for (int i = 0; i < 8; i++) { S += rs[i]; Q += rq[i]; }

    float mu  = S * (1.f / 1024.f);
    float var = Q * (1.f / 1024.f) - mu * mu;
    float inv = rsqrtf(var + 1e-5f);

    float4 gg = *(const float4*)(g + t * 4);
    float4 bb = *(const float4*)(b + t * 4);
    float4 o;
    o.x = (v.x - mu) * inv * gg.x + bb.x;
    o.y = (v.y - mu) * inv * gg.y + bb.y;
    o.z = (v.z - mu) * inv * gg.z + bb.z;
    o.w = (v.w - mu) * inv * gg.w + bb.w;
    *(float4*)(O + (long)row * D_MODEL + t * 4) = o;
}

// ---------------------------------------------------------------------------
extern "C" void kernel_launch(void* const* d_in, const int* in_sizes, int n_in,
                              void* d_out, int out_size)
{
    const float* query   = (const float*)d_in[0];
    const float* ent_emb = (const float*)d_in[1];
    const int*   idx     = (const int*)  d_in[2];
    const float* WQ_w = (const float*)d_in[4];
    const float* WQ_b = (const float*)d_in[5];
    const float* WK_w = (const float*)d_in[6];
    const float* WK_b = (const float*)d_in[7];
    const float* WO_w = (const float*)d_in[8];
    const float* WO_b = (const float*)d_in[9];
    const float* ln_g = (const float*)d_in[10];
    const float* ln_b = (const float*)d_in[11];
    float* out = (float*)d_out;

    __half *qh, *A12h, *A12l, *WKTh, *WKTl, *Gh, *T12, *EQEO, *EOT, *Wh;
    float *sb, *vb, *b2, *P;
    cudaGetSymbolAddress((void**)&qh,   g_qh);
    cudaGetSymbolAddress((void**)&A12h, g_A12h); cudaGetSymbolAddress((void**)&A12l, g_A12l);
    cudaGetSymbolAddress((void**)&WKTh, g_WKTh); cudaGetSymbolAddress((void**)&WKTl, g_WKTl);
    cudaGetSymbolAddress((void**)&Gh,   g_Gh);
    cudaGetSymbolAddress((void**)&T12,  g_T12);
    cudaGetSymbolAddress((void**)&EQEO, g_EQEO);
    cudaGetSymbolAddress((void**)&EOT,  g_EOT);
    cudaGetSymbolAddress((void**)&Wh,   g_Wh);
    cudaGetSymbolAddress((void**)&sb,   g_sb);
    cudaGetSymbolAddress((void**)&vb,   g_vb);
    cudaGetSymbolAddress((void**)&b2,   g_b2);
    cudaGetSymbolAddress((void**)&P,    g_P);

    cudaFuncSetAttribute((const void*)gemm2<true >,
        cudaFuncAttributeMaxDynamicSharedMemorySize, GSMEM_G);
    cudaFuncSetAttribute((const void*)gemm2<false>,
        cudaFuncAttributeMaxDynamicSharedMemorySize, GSMEM_G);
    cudaFuncSetAttribute((const void*)sgemm_softmax,
        cudaFuncAttributeMaxDynamicSharedMemorySize, GSMEM_F);

    const int DD4 = D_MODEL * D_MODEL / 4;
    const long DD = (long)D_MODEL * D_MODEL;

    // 0. input preprocessing
    tohalf<<<(ML * D_MODEL / 4 + 255) / 256, 256>>>(query, qh, ML * D_MODEL / 4);
    split_tr<<<dim3(32, 32), dim3(32, 8)>>>(WQ_w, A12h, A12l);
    split_f16<<<(DD4 + 255) / 256, 256>>>(WO_w, A12h + DD, A12l + DD, DD4);
    split_tr<<<dim3(32, 32), dim3(32, 8)>>>(WK_w, WKTh, WKTl);
    prep_vec<<<3073, 256>>>(A12h, A12l, WO_w, WKTh, WKTl, WK_b, WQ_b, b2, vb);
    gather_sb<<<MB, 256>>>(ent_emb, idx, vb, Gh, sb);

    // 1. merged weight product: [T1;T2] = [WQ^T;WO] @ WK  (1-term, BK=32)
    gemm2<true><<<dim3(8, 16, 1), 256, GSMEM_G>>>(
        A12h, 0, WKTh, 0, D_MODEL, nullptr, T12, 0,
        D_MODEL, D_MODEL, nullptr, 0);

    // 2. EQEO = G @ [T1;T2]^T + bias2   [4096 x 2048 x 1024]
    gemm2<true><<<dim3(16, 32, 1), 256, GSMEM_G>>>(
        Gh, 0, T12, 0, D_MODEL, nullptr, EQEO, 0,
        2048, D_MODEL, b2, 0);

    // 3. fused scores + masked softmax -> fp16 weights
    sgemm_softmax<<<dim3(1, 16, BATCH), 256, GSMEM_F>>>(
        qh, EQEO, sb, idx, Wh);

    // 4. EOT[b] = EO[b]^T
    transpose_f16<<<dim3(32, 8, BATCH), dim3(32, 8)>>>(EQEO, EOT);

    // 5. P[b] = W[b] @ EOT[b]^T + bO   [16 x (1024 x 1024 x 256)]
    gemm2<false><<<dim3(8, 8, BATCH), 256, GSMEM_G>>>(
        Wh, (long)LQ * NBE, EOT, (long)D_MODEL * NBE, NBE,
        P, nullptr, (long)LQ * D_MODEL, D_MODEL, NBE, WO_b, 0);

    // 6. LayerNorm -> out
    layernorm_k<<<ML, 256>>>(P, ln_g, ln_b, out);
}

// round 15
// speedup vs baseline: 1.1266x; 1.0307x over previous
#include <cuda_runtime.h>
#include <cuda_bf16.h>
#include <cuda_fp16.h>
#include <cstdint>

// ---------------------------------------------------------------------------
// Problem constants
// ---------------------------------------------------------------------------
#define D_MODEL 1024
#define BATCH   16
#define LQ      1024
#define NBE     256
#define ML (BATCH * LQ)    // 16384
#define MB (BATCH * NBE)   // 4096

// ---------------------------------------------------------------------------
// Scratch (__device__ globals; no allocation anywhere)
// ---------------------------------------------------------------------------
__device__ __half  g_qh  [ML * D_MODEL];                 // query fp16 (1 plane)
__device__ __half  g_A12h[2048 * D_MODEL];               // [WQ^T ; WO] hi plane
__device__ __half  g_A12l[2048 * D_MODEL];               // lo plane (bias vectors only)
__device__ __half  g_WKTh[D_MODEL * D_MODEL];            // WK^T hi
__device__ __half  g_WKTl[D_MODEL * D_MODEL];            // WK^T lo (bias vectors only)
__device__ __half  g_Gh  [MB * D_MODEL];                 // gathered ents (1 plane)
__device__ __half  g_T12 [2048 * D_MODEL];               // [T1; T2] fp16
__device__ __half  g_EQEO[MB * 2048];                    // [EQ | EO] fp16
__device__ __half  g_EOT [MB * D_MODEL];                 // EO^T per batch
__device__ float   g_sb  [MB];                           // bQ.ENT score bias
__device__ float   g_vb  [1025];                         // WK^T bQ, [1024]=bQ.bK
__device__ float   g_b2  [2048];                         // [bK@WQ | bK@WO^T]
__device__ __half  g_Wh  [ML * NBE];                     // softmax wts fp16 (1 plane)
__device__ __half  g_Ph  [ML * D_MODEL];                 // pre-LN fp16

// ---------------------------------------------------------------------------
// Helpers
// ---------------------------------------------------------------------------
__device__ __forceinline__ void split1h(float x, __half& h, __half& l) {
    h = __float2half_rn(x);
    l = __float2half_rn(x - __half2float(h));
}

__device__ __forceinline__ void cp16(uint32_t dst, const void* src) {
    asm volatile("cp.async.cg.shared.global [%0], [%1], 16;"
                 :: "r"(dst), "l"(src) : "memory");
}
__device__ __forceinline__ void ldsm4(uint32_t* r, uint32_t addr) {
    asm volatile("ldmatrix.sync.aligned.m8n8.x4.shared.b16 {%0,%1,%2,%3}, [%4];"
                 : "=r"(r[0]), "=r"(r[1]), "=r"(r[2]), "=r"(r[3]) : "r"(addr));
}
__device__ __forceinline__ void mma_f16(float* c, const uint32_t* a,
                                        uint32_t b0, uint32_t b1) {
    asm volatile(
        "mma.sync.aligned.m16n8k16.row.col.f32.f16.f16.f32 "
        "{%0,%1,%2,%3}, {%4,%5,%6,%7}, {%8,%9}, {%0,%1,%2,%3};"
        : "+f"(c[0]), "+f"(c[1]), "+f"(c[2]), "+f"(c[3])
        : "r"(a[0]), "r"(a[1]), "r"(a[2]), "r"(a[3]), "r"(b0), "r"(b1));
}

#define BKC 32
#define SKB 80                        // smem row stride bytes (40 halves)
#define PLANE_B (128 * SKB)           // 10240 B per plane per stage

// ---------------------------------------------------------------------------
// gemm2: fp16 NT GEMM (1-term): C[bz][M,N] = A @ B^T (+bias)
// A fp16 plane (lda=K), B fp16 plane (row stride ldb).
// Output fp16 (F16OUT) or fp32.  bias[bz*sBias + col].
// CTA 128x128, BK=32, 8 warps (2x4, warp tile 64x32),
// 2-stage cp.async pipeline, 256 threads, 2 CTAs/SM.
// ---------------------------------------------------------------------------
#define STAGE_B (2 * PLANE_B)         // A + B
#define GSMEM_G (2 * STAGE_B)         // 40960 B

template<bool F16OUT>
__global__ void __launch_bounds__(256, 2) gemm2(
    const __half* __restrict__ Ap, long sA,
    const __half* __restrict__ Bp, long sB, int ldb,
    float* __restrict__ Cf, __half* __restrict__ Ch, long sC,
    int N, int K,
    const float* __restrict__ bias, long sBias)
{
    extern __shared__ char smc[];
    const uint32_t smb = (uint32_t)__cvta_generic_to_shared(smc);

    const int tid  = threadIdx.x;
    const int wid  = tid >> 5;
    const int lane = tid & 31;
    const int wm   = wid >> 2;
    const int wn   = wid & 3;
    const int gq   = lane >> 2;
    const int tg   = lane & 3;

    const int mtile = blockIdx.y * 128;
    const int ntile = blockIdx.x * 128;
    const int bz    = blockIdx.z;
    Ap += (long)bz * sA;
    Bp += (long)bz * sB;

    const int nch = K >> 5;

    float acc[4][4][4];
#pragma unroll
    for (int i = 0; i < 4; i++)
#pragma unroll
        for (int j = 0; j < 4; j++)
#pragma unroll
            for (int q = 0; q < 4; q++) acc[i][j][q] = 0.f;

    const int lrow = tid >> 2;
    const int lseg = tid & 3;
    const long aoff = (long)(mtile + lrow) * K + lseg * 8;
    const long boff = (long)(ntile + lrow) * ldb + lseg * 8;
    const long ahalf = (long)64 * K;
    const long bhalf = (long)64 * ldb;
    const uint32_t sdst = lrow * SKB + lseg * 16;
    const uint32_t shalf = 64 * SKB;

    auto load_chunk = [&](int c, int s) {
        const long kofs = (long)c * BKC;
        const uint32_t sb = smb + s * STAGE_B + sdst;
        cp16(sb,                     Ap + aoff + kofs);
        cp16(sb + shalf,             Ap + aoff + ahalf + kofs);
        cp16(sb + PLANE_B,           Bp + boff + kofs);
        cp16(sb + PLANE_B + shalf,   Bp + boff + bhalf + kofs);
    };

    load_chunk(0, 0);
    asm volatile("cp.async.commit_group;" ::: "memory");

    const int lr = (lane & 7) + ((lane >> 3) & 1) * 8;
    const int lc = ((lane >> 4) & 1) * 16;

    for (int c = 0; c < nch; c++) {
        const int s = c & 1;
        if (c + 1 < nch) {
            load_chunk(c + 1, s ^ 1);
            asm volatile("cp.async.commit_group;" ::: "memory");
            asm volatile("cp.async.wait_group 1;" ::: "memory");
        } else {
            asm volatile("cp.async.wait_group 0;" ::: "memory");
        }
        __syncthreads();
        const uint32_t stb = smb + s * STAGE_B;

#pragma unroll
        for (int kk = 0; kk < 2; kk++) {
            uint32_t bh[2][4];
#pragma unroll
            for (int h = 0; h < 2; h++) {
                uint32_t bd = stb + PLANE_B
                            + (uint32_t)(wn * 32 + h * 16 + lr) * SKB + kk * 32 + lc;
                ldsm4(bh[h], bd);
            }
#pragma unroll
            for (int mp = 0; mp < 2; mp++) {
                uint32_t ah[2][4];
#pragma unroll
                for (int m2 = 0; m2 < 2; m2++) {
                    uint32_t ad = stb
                        + (uint32_t)(wm * 64 + (mp * 2 + m2) * 16 + lr) * SKB
                        + kk * 32 + lc;
                    ldsm4(ah[m2], ad);
                }
#pragma unroll
                for (int m2 = 0; m2 < 2; m2++)
#pragma unroll
                    for (int h = 0; h < 2; h++)
#pragma unroll
                        for (int j = 0; j < 2; j++)
                            mma_f16(acc[mp * 2 + m2][h * 2 + j],
                                    ah[m2], bh[h][j], bh[h][j + 2]);
            }
        }
        __syncthreads();
    }

#pragma unroll
    for (int mt = 0; mt < 4; mt++) {
        const int r0 = mtile + wm * 64 + mt * 16 + gq;
#pragma unroll
        for (int nt = 0; nt < 4; nt++) {
            const int col = ntile + wn * 32 + nt * 8 + tg * 2;
            float bx = 0.f, by = 0.f;
            if (bias != nullptr) {
                float2 bb = *(const float2*)(bias + bz * sBias + col);
                bx = bb.x; by = bb.y;
            }
            float o00 = acc[mt][nt][0] + bx;
            float o01 = acc[mt][nt][1] + by;
            float o10 = acc[mt][nt][2] + bx;
            float o11 = acc[mt][nt][3] + by;
            const long i0 = (long)bz * sC + (long)r0 * N + col;
            const long i1 = i0 + (long)8 * N;
            if (F16OUT) {
                __half2 p0, p1;
                p0.x = __float2half_rn(o00); p0.y = __float2half_rn(o01);
                p1.x = __float2half_rn(o10); p1.y = __float2half_rn(o11);
                *(__half2*)(Ch + i0) = p0;
                *(__half2*)(Ch + i1) = p1;
            } else {
                *(float2*)(Cf + i0) = make_float2(o00, o01);
                *(float2*)(Cf + i1) = make_float2(o10, o11);
            }
        }
    }
}

// ---------------------------------------------------------------------------
// sgemm_softmax: fused scores + masked softmax (BK=32, SKB=80).
// W[bz][64 rows][256] = softmax_row( q @ EQ^T + sb - 1e5*mask ) * d^-0.5
// ---------------------------------------------------------------------------
#define APL_B (64 * SKB)              // 5120 B
#define BPL_B (256 * SKB)             // 20480 B
#define STG_F (APL_B + BPL_B)         // 25600 B
#define GSMEM_F (2 * STG_F)           // 51200 B

__global__ void __launch_bounds__(256, 2) sgemm_softmax(
    const __half* __restrict__ Q,
    const __half* __restrict__ EQEO,
    const float* __restrict__ sb,
    const int* __restrict__ idx,
    __half* __restrict__ Wout)
{
    extern __shared__ char smc[];
    const uint32_t smb = (uint32_t)__cvta_generic_to_shared(smc);
    __shared__ float redm[64][9];
    __shared__ float reds[64][9];

    const int tid  = threadIdx.x;
    const int wid  = tid >> 5;
    const int lane = tid & 31;
    const int gq   = lane >> 2;
    const int tg   = lane & 3;

    const int mtile = blockIdx.y * 64;
    const int bz    = blockIdx.z;
    const int K = D_MODEL, ldb = 2048;

    const __half* A = Q    + (long)bz * LQ * D_MODEL;
    const __half* B = EQEO + (long)bz * NBE * 2048;

    float acc[4][4][4];
#pragma unroll
    for (int i = 0; i < 4; i++)
#pragma unroll
        for (int j = 0; j < 4; j++)
#pragma unroll
            for (int q = 0; q < 4; q++) acc[i][j][q] = 0.f;

    const int lrow = tid >> 2;
    const int lseg = tid & 3;
    const long aoff = (long)(mtile + lrow) * K + lseg * 8;
    const long boff = (long)lrow * ldb + lseg * 8;
    const uint32_t sdst = lrow * SKB + lseg * 16;
    const uint32_t s64 = 64 * SKB;

    auto load_chunk = [&](int c, int s) {
        const long kofs = (long)c * BKC;
        const uint32_t sbs = smb + s * STG_F + sdst;
        cp16(sbs, A + aoff + kofs);
        const uint32_t bb = sbs + APL_B;
        cp16(bb,           B + boff + kofs);
        cp16(bb + s64,     B + boff + (long)64  * ldb + kofs);
        cp16(bb + 2 * s64, B + boff + (long)128 * ldb + kofs);
        cp16(bb + 3 * s64, B + boff + (long)192 * ldb + kofs);
    };

    load_chunk(0, 0);
    asm volatile("cp.async.commit_group;" ::: "memory");

    const int lr = (lane & 7) + ((lane >> 3) & 1) * 8;
    const int lc = ((lane >> 4) & 1) * 16;
    const int nch = K >> 5;

    for (int c = 0; c < nch; c++) {
        const int s = c & 1;
        if (c + 1 < nch) {
            load_chunk(c + 1, s ^ 1);
            asm volatile("cp.async.commit_group;" ::: "memory");
            asm volatile("cp.async.wait_group 1;" ::: "memory");
        } else {
            asm volatile("cp.async.wait_group 0;" ::: "memory");
        }
        __syncthreads();
        const uint32_t stb = smb + s * STG_F;

#pragma unroll
        for (int kk = 0; kk < 2; kk++) {
            uint32_t bh[2][4];
#pragma unroll
            for (int h = 0; h < 2; h++) {
                uint32_t bd = stb + APL_B
                            + (uint32_t)(wid * 32 + h * 16 + lr) * SKB + kk * 32 + lc;
                ldsm4(bh[h], bd);
            }
#pragma unroll
            for (int mp = 0; mp < 2; mp++) {
                uint32_t ah[2][4];
#pragma unroll
                for (int m2 = 0; m2 < 2; m2++) {
                    uint32_t ad = stb
                        + (uint32_t)((mp * 2 + m2) * 16 + lr) * SKB + kk * 32 + lc;
                    ldsm4(ah[m2], ad);
                }
#pragma unroll
                for (int m2 = 0; m2 < 2; m2++)
#pragma unroll
                    for (int h = 0; h < 2; h++)
#pragma unroll
                        for (int j = 0; j < 2; j++)
                            mma_f16(acc[mp * 2 + m2][h * 2 + j],
                                    ah[m2], bh[h][j], bh[h][j + 2]);
            }
        }
        __syncthreads();
    }

    // ---- fused masked softmax epilogue ----
    const float* sbb = sb + bz * NBE;
    const int*  idxb = idx + bz * NBE;

#pragma unroll
    for (int nt = 0; nt < 4; nt++) {
        const int col = wid * 32 + nt * 8 + tg * 2;
        float2 bb = *(const float2*)(sbb + col);
        bool m0 = idxb[col] < 0;
        bool m1 = idxb[col + 1] < 0;
#pragma unroll
        for (int mt = 0; mt < 4; mt++) {
            acc[mt][nt][0] = m0 ? -100000.f : acc[mt][nt][0] + bb.x;
            acc[mt][nt][1] = m1 ? -100000.f : acc[mt][nt][1] + bb.y;
            acc[mt][nt][2] = m0 ? -100000.f : acc[mt][nt][2] + bb.x;
            acc[mt][nt][3] = m1 ? -100000.f : acc[mt][nt][3] + bb.y;
        }
    }

#pragma unroll
    for (int mt = 0; mt < 4; mt++)
#pragma unroll
        for (int rh = 0; rh < 2; rh++) {
            float m = -3.4e38f;
#pragma unroll
            for (int nt = 0; nt < 4; nt++) {
                m = fmaxf(m, acc[mt][nt][rh * 2]);
                m = fmaxf(m, acc[mt][nt][rh * 2 + 1]);
            }
            m = fmaxf(m, __shfl_xor_sync(0xffffffffu, m, 1));
            m = fmaxf(m, __shfl_xor_sync(0xffffffffu, m, 2));
            if (tg == 0) redm[mt * 16 + rh * 8 + gq][wid] = m;
        }
    __syncthreads();

#pragma unroll
    for (int mt = 0; mt < 4; mt++)
#pragma unroll
        for (int rh = 0; rh < 2; rh++) {
            const int rl = mt * 16 + rh * 8 + gq;
            float mall = redm[rl][0];
#pragma unroll
            for (int w = 1; w < 8; w++) mall = fmaxf(mall, redm[rl][w]);
            float ssum = 0.f;
#pragma unroll
            for (int nt = 0; nt < 4; nt++) {
                float e0 = expf(acc[mt][nt][rh * 2]     - mall);
                float e1 = expf(acc[mt][nt][rh * 2 + 1] - mall);
                acc[mt][nt][rh * 2]     = e0;
                acc[mt][nt][rh * 2 + 1] = e1;
                ssum += e0 + e1;
            }
            ssum += __shfl_xor_sync(0xffffffffu, ssum, 1);
            ssum += __shfl_xor_sync(0xffffffffu, ssum, 2);
            if (tg == 0) reds[rl][wid] = ssum;
        }
    __syncthreads();

#pragma unroll
    for (int mt = 0; mt < 4; mt++)
#pragma unroll
        for (int rh = 0; rh < 2; rh++) {
            const int rl = mt * 16 + rh * 8 + gq;
            float sum = reds[rl][0];
#pragma unroll
            for (int w = 1; w < 8; w++) sum += reds[rl][w];
            const float inv = 0.03125f / sum;
            const long rowoff = (long)(bz * LQ + mtile + rl) * NBE;
#pragma unroll
            for (int nt = 0; nt < 4; nt++) {
                const int col = wid * 32 + nt * 8 + tg * 2;
                __half2 p;
                p.x = __float2half_rn(acc[mt][nt][rh * 2]     * inv);
                p.y = __float2half_rn(acc[mt][nt][rh * 2 + 1] * inv);
                *(__half2*)(Wout + rowoff + col) = p;
            }
        }
}

// ---------------------------------------------------------------------------
// prep_all: merged input conversion kernel (one launch).
//   blocks [0, 16384)       : query fp32 -> qh fp16
//   blocks [16384, 17408)   : WO fp32 -> A12h/A12l rows 1024..2047 (split)
//   blocks [17408, 18432)   : WQ -> split+transpose into A12 rows 0..1023
//   blocks [18432, 19456)   : WK -> split+transpose into WKT   (CLOCK CANARY sections)
// 256 threads per block.
// ---------------------------------------------------------------------------
__global__ void prep_all(const float* __restrict__ query,
                         const float* __restrict__ WO,
                         const float* __restrict__ WQ,
                         const float* __restrict__ WK,
                         __half* __restrict__ qh,
                         __half* __restrict__ A12h, __half* __restrict__ A12l,
                         __half* __restrict__ WKTh, __half* __restrict__ WKTl)
{
    __shared__ float t[32][33];
    const int b   = blockIdx.x;
    const int tid = threadIdx.x;
    const long DD = (long)D_MODEL * D_MODEL;

    if (b < 16384) {                          // query -> fp16
        const int i = b * 256 + tid;          // float4 index
        float4 v = ((const float4*)query)[i];
        __half hh[4];
        hh[0] = __float2half_rn(v.x); hh[1] = __float2half_rn(v.y);
        hh[2] = __float2half_rn(v.z); hh[3] = __float2half_rn(v.w);
        ((uint2*)qh)[i] = *(uint2*)hh;
    } else if (b < 17408) {                   // WO split -> A12 rows 1024+
        const int i = (b - 16384) * 256 + tid;
        float4 v = ((const float4*)WO)[i];
        __half hh[4], ll[4];
        split1h(v.x, hh[0], ll[0]); split1h(v.y, hh[1], ll[1]);
        split1h(v.z, hh[2], ll[2]); split1h(v.w, hh[3], ll[3]);
        ((uint2*)(A12h + DD))[i] = *(uint2*)hh;
        ((uint2*)(A12l + DD))[i] = *(uint2*)ll;
    } else {                                  // transpose+split WQ or WK
        const bool isWK = b >= 18432;
        const int bb = isWK ? b - 18432 : b - 17408;
        const float* W = isWK ? WK : WQ;
        __half* Th = isWK ? WKTh : A12h;
        __half* Tl = isWK ? WKTl : A12l;
        const int c0 = (bb & 31) * 32;
        const int r0 = (bb >> 5) * 32;
        const int tx = tid & 31, ty = tid >> 5;   // ty 0..7
#pragma unroll
        for (int i = 0; i < 32; i += 8)
            t[ty + i][tx] = W[(long)(r0 + ty + i) * D_MODEL + c0 + tx];
        __syncthreads();
#pragma unroll
        for (int i = 0; i < 32; i += 8) {
            float v = t[tx][ty + i];
            __half h, l;
            split1h(v, h, l);
            const long o = (long)(c0 + ty + i) * D_MODEL + r0 + tx;
            Th[o] = h;  Tl[o] = l;
        }
    }
}

// ---------------------------------------------------------------------------
// prep_vec: b2[0:1024]=bK@WQ, b2[1024:2048]=bK@WO^T, vb[0:1024]=WK^T bQ,
// vb[1024]=bQ.bK.  One block per output element.  (hi+lo planes, exact)
// ---------------------------------------------------------------------------
__global__ void prep_vec(const __half* __restrict__ A12h,
                         const __half* __restrict__ A12l,
                         const float* __restrict__ WO,
                         const __half* __restrict__ WKTh,
                         const __half* __restrict__ WKTl,
                         const float* __restrict__ bK,
                         const float* __restrict__ bQ,
                         float* __restrict__ b2, float* __restrict__ vb)
{
    const int n = blockIdx.x;
    const int t = threadIdx.x;
    float s = 0.f;

    if (n < 1024) {
        const uint2 h2 = ((const uint2*)(A12h + (long)n * D_MODEL))[t];
        const uint2 l2 = ((const uint2*)(A12l + (long)n * D_MODEL))[t];
        const __half* hp = (const __half*)&h2;
        const __half* lp = (const __half*)&l2;
        float4 b = ((const float4*)bK)[t];
        s = (__half2float(hp[0]) + __half2float(lp[0])) * b.x
          + (__half2float(hp[1]) + __half2float(lp[1])) * b.y
          + (__half2float(hp[2]) + __half2float(lp[2])) * b.z
          + (__half2float(hp[3]) + __half2float(lp[3])) * b.w;
    } else if (n < 2048) {
        float4 w = ((const float4*)(WO + (long)(n - 1024) * D_MODEL))[t];
        float4 b = ((const float4*)bK)[t];
        s = w.x * b.x + w.y * b.y + w.z * b.z + w.w * b.w;
    } else if (n < 3072) {
        const uint2 h2 = ((const uint2*)(WKTh + (long)(n - 2048) * D_MODEL))[t];
        const uint2 l2 = ((const uint2*)(WKTl + (long)(n - 2048) * D_MODEL))[t];
        const __half* hp = (const __half*)&h2;
        const __half* lp = (const __half*)&l2;
        float4 b = ((const float4*)bQ)[t];
        s = (__half2float(hp[0]) + __half2float(lp[0])) * b.x
          + (__half2float(hp[1]) + __half2float(lp[1])) * b.y
          + (__half2float(hp[2]) + __half2float(lp[2])) * b.z
          + (__half2float(hp[3]) + __half2float(lp[3])) * b.w;
    } else {
        float4 q = ((const float4*)bQ)[t];
        float4 b = ((const float4*)bK)[t];
        s = q.x * b.x + q.y * b.y + q.z * b.z + q.w * b.w;
    }

    __shared__ float red[8];
#pragma unroll
    for (int o = 16; o; o >>= 1) s += __shfl_xor_sync(0xffffffffu, s, o);
    if ((t & 31) == 0) red[t >> 5] = s;
    __syncthreads();
    if (t == 0) {
        float tot = 0.f;
#pragma unroll
        for (int i = 0; i < 8; i++) tot += red[i];
        if (n < 2048)      b2[n] = tot;
        else if (n < 3072) vb[n - 2048] = tot;
        else               vb[1024] = tot;
    }
}

// ---------------------------------------------------------------------------
// gather (single fp16 plane) + score-bias
// ---------------------------------------------------------------------------
__global__ void gather_sb(const float* __restrict__ E,
                          const int* __restrict__ idx,
                          const float* __restrict__ vb,
                          __half* __restrict__ Gh,
                          float* __restrict__ sb)
{
    const int r = blockIdx.x;
    int s = idx[r];
    if (s < 0) s = 0;
    const int i = threadIdx.x;
    float4 v = ((const float4*)(E + (long)s * D_MODEL))[i];
    __half hh[4];
    hh[0] = __float2half_rn(v.x); hh[1] = __float2half_rn(v.y);
    hh[2] = __float2half_rn(v.z); hh[3] = __float2half_rn(v.w);
    ((uint2*)(Gh + (long)r * D_MODEL))[i] = *(uint2*)hh;

    float4 w = ((const float4*)vb)[i];
    float d = v.x * w.x + v.y * w.y + v.z * w.z + v.w * w.w;
    __shared__ float red[8];
#pragma unroll
    for (int o = 16; o; o >>= 1) d += __shfl_xor_sync(0xffffffffu, d, o);
    if ((i & 31) == 0) red[i >> 5] = d;
    __syncthreads();
    if (i == 0) {
        float tot = vb[1024];
#pragma unroll
        for (int k = 0; k < 8; k++) tot += red[k];
        sb[r] = tot;
    }
}

// ---------------------------------------------------------------------------
// per-batch fp16 transpose of the EO half of EQEO -> EOT[b] (D x NBE)
// ---------------------------------------------------------------------------
__global__ void transpose_f16(const __half* __restrict__ EQEO,
                              __half* __restrict__ EOT)
{
    __shared__ __half t[32][34];
    const int b  = blockIdx.z;
    const int c0 = blockIdx.x * 32;
    const int r0 = blockIdx.y * 32;
    const int tx = threadIdx.x, ty = threadIdx.y;
#pragma unroll
    for (int i = 0; i < 32; i += 8)
        t[ty + i][tx] = EQEO[(long)(b * NBE + r0 + ty + i) * 2048 + 1024 + c0 + tx];
    __syncthreads();
#pragma unroll
    for (int i = 0; i < 32; i += 8)
        EOT[(long)b * NBE * D_MODEL + (long)(c0 + ty + i) * NBE + r0 + tx]
            = t[tx][ty + i];
}

// ---------------------------------------------------------------------------
// Row LayerNorm over D=1024 reading fp16 input (biased var, eps=1e-5).
// ---------------------------------------------------------------------------
__global__ void layernorm_h(const __half* __restrict__ X,
                            const float* __restrict__ g,
                            const float* __restrict__ b,
                            float* __restrict__ O)
{
    const int row = blockIdx.x;
    const int t   = threadIdx.x;

    const uint2 x2 = ((const uint2*)(X + (long)row * D_MODEL))[t];
    const __half* xp = (const __half*)&x2;
    float v0 = __half2float(xp[0]), v1 = __half2float(xp[1]);
    float v2 = __half2float(xp[2]), v3 = __half2float(xp[3]);

    float s  = v0 + v1 + v2 + v3;
    float sq = v0 * v0 + v1 * v1 + v2 * v2 + v3 * v3;

    __shared__ float rs[8], rq[8];
#pragma unroll
    for (int o = 16; o; o >>= 1) {
        s  += __shfl_xor_sync(0xffffffffu, s,  o);
        sq += __shfl_xor_sync(0xffffffffu, sq, o);
    }
    if ((t & 31) == 0) { rs[t >> 5] = s; rq[t >> 5] = sq; }
    __syncthreads();
    float S = 0.f, Q = 0.f;
#pragma unroll
    for (int i = 0; i < 8; i++) { S += rs[i]; Q += rq[i]; }

    float mu  = S * (1.f / 1024.f);
    float var = Q * (1.f / 1024.f) - mu * mu;
    float inv = rsqrtf(var + 1e-5f);

    float4 gg = *(const float4*)(g + t * 4);
    float4 bb = *(const float4*)(b + t * 4);
    float4 o;
    o.x = (v0 - mu) * inv * gg.x + bb.x;
    o.y = (v1 - mu) * inv * gg.y + bb.y;
    o.z = (v2 - mu) * inv * gg.z + bb.z;
    o.w = (v3 - mu) * inv * gg.w + bb.w;
    *(float4*)(O + (long)row * D_MODEL + t * 4) = o;
}

// ---------------------------------------------------------------------------
extern "C" void kernel_launch(void* const* d_in, const int* in_sizes, int n_in,
                              void* d_out, int out_size)
{
    const float* query   = (const float*)d_in[0];
    const float* ent_emb = (const float*)d_in[1];
    const int*   idx     = (const int*)  d_in[2];
    const float* WQ_w = (const float*)d_in[4];
    const float* WQ_b = (const float*)d_in[5];
    const float* WK_w = (const float*)d_in[6];
    const float* WK_b = (const float*)d_in[7];
    const float* WO_w = (const float*)d_in[8];
    const float* WO_b = (const float*)d_in[9];
    const float* ln_g = (const float*)d_in[10];
    const float* ln_b = (const float*)d_in[11];
    float* out = (float*)d_out;

    __half *qh, *A12h, *A12l, *WKTh, *WKTl, *Gh, *T12, *EQEO, *EOT, *Wh, *Ph;
    float *sb, *vb, *b2;
    cudaGetSymbolAddress((void**)&qh,   g_qh);
    cudaGetSymbolAddress((void**)&A12h, g_A12h); cudaGetSymbolAddress((void**)&A12l, g_A12l);
    cudaGetSymbolAddress((void**)&WKTh, g_WKTh); cudaGetSymbolAddress((void**)&WKTl, g_WKTl);
    cudaGetSymbolAddress((void**)&Gh,   g_Gh);
    cudaGetSymbolAddress((void**)&T12,  g_T12);
    cudaGetSymbolAddress((void**)&EQEO, g_EQEO);
    cudaGetSymbolAddress((void**)&EOT,  g_EOT);
    cudaGetSymbolAddress((void**)&Wh,   g_Wh);
    cudaGetSymbolAddress((void**)&Ph,   g_Ph);
    cudaGetSymbolAddress((void**)&sb,   g_sb);
    cudaGetSymbolAddress((void**)&vb,   g_vb);
    cudaGetSymbolAddress((void**)&b2,   g_b2);

    cudaFuncSetAttribute((const void*)gemm2<true >,
        cudaFuncAttributeMaxDynamicSharedMemorySize, GSMEM_G);
    cudaFuncSetAttribute((const void*)gemm2<false>,
        cudaFuncAttributeMaxDynamicSharedMemorySize, GSMEM_G);
    cudaFuncSetAttribute((const void*)sgemm_softmax,
        cudaFuncAttributeMaxDynamicSharedMemorySize, GSMEM_F);

    // 0. merged input preprocessing (query fp16, WO split, WQ/WK transpose-split)
    prep_all<<<19456, 256>>>(query, WO_w, WQ_w, WK_w,
                             qh, A12h, A12l, WKTh, WKTl);
    prep_vec<<<3073, 256>>>(A12h, A12l, WO_w, WKTh, WKTl, WK_b, WQ_b, b2, vb);
    gather_sb<<<MB, 256>>>(ent_emb, idx, vb, Gh, sb);

    // 1. merged weight product: [T1;T2] = [WQ^T;WO] @ WK  (1-term, BK=32)
    gemm2<true><<<dim3(8, 16, 1), 256, GSMEM_G>>>(
        A12h, 0, WKTh, 0, D_MODEL, nullptr, T12, 0,
        D_MODEL, D_MODEL, nullptr, 0);

    // 2. EQEO = G @ [T1;T2]^T + bias2   [4096 x 2048 x 1024]
    gemm2<true><<<dim3(16, 32, 1), 256, GSMEM_G>>>(
        Gh, 0, T12, 0, D_MODEL, nullptr, EQEO, 0,
        2048, D_MODEL, b2, 0);

    // 3. fused scores + masked softmax -> fp16 weights
    sgemm_softmax<<<dim3(1, 16, BATCH), 256, GSMEM_F>>>(
        qh, EQEO, sb, idx, Wh);

    // 4. EOT[b] = EO[b]^T
    transpose_f16<<<dim3(32, 8, BATCH), dim3(32, 8)>>>(EQEO, EOT);

    // 5. P[b] = W[b] @ EOT[b]^T + bO  -> fp16
    gemm2<true><<<dim3(8, 8, BATCH), 256, GSMEM_G>>>(
        Wh, (long)LQ * NBE, EOT, (long)D_MODEL * NBE, NBE,
        nullptr, Ph, (long)LQ * D_MODEL, D_MODEL, NBE, WO_b, 0);

    // 6. LayerNorm (fp16 in) -> fp32 out
    layernorm_h<<<ML, 256>>>(Ph, ln_g, ln_b, out);
}

// round 16
// speedup vs baseline: 1.1322x; 1.0050x over previous
#include <cuda_runtime.h>
#include <cuda_bf16.h>
#include <cuda_fp16.h>
#include <cstdint>

// ---------------------------------------------------------------------------
// Problem constants
// ---------------------------------------------------------------------------
#define D_MODEL 1024
#define BATCH   16
#define LQ      1024
#define NBE     256
#define ML (BATCH * LQ)    // 16384
#define MB (BATCH * NBE)   // 4096

// ---------------------------------------------------------------------------
// Scratch (__device__ globals; no allocation anywhere)
// ---------------------------------------------------------------------------
__device__ __half  g_qh  [ML * D_MODEL];                 // query fp16 (1 plane)
__device__ __half  g_A12h[2048 * D_MODEL];               // [WQ^T ; WO] hi plane
__device__ __half  g_A12l[2048 * D_MODEL];               // lo plane (bias vectors only)
__device__ __half  g_WKTh[D_MODEL * D_MODEL];            // WK^T hi
__device__ __half  g_WKTl[D_MODEL * D_MODEL];            // WK^T lo (bias vectors only)
__device__ __half  g_Gh  [MB * D_MODEL];                 // gathered ents (1 plane)
__device__ __half  g_T12 [2048 * D_MODEL];               // [T1; T2] fp16
__device__ __half  g_EQEO[MB * 2048];                    // [EQ | EO] fp16
__device__ __half  g_EOT [MB * D_MODEL];                 // EO^T per batch
__device__ float   g_sb  [MB];                           // bQ.ENT score bias
__device__ float   g_vb  [1025];                         // WK^T bQ, [1024]=bQ.bK
__device__ float   g_b2  [2048];                         // [bK@WQ | bK@WO^T]
__device__ __half  g_Wh  [ML * NBE];                     // softmax wts fp16 (1 plane)
__device__ __half  g_Ph  [ML * D_MODEL];                 // pre-LN fp16

// ---------------------------------------------------------------------------
// Helpers
// ---------------------------------------------------------------------------
__device__ __forceinline__ void split1h(float x, __half& h, __half& l) {
    h = __float2half_rn(x);
    l = __float2half_rn(x - __half2float(h));
}

__device__ __forceinline__ void cp16(uint32_t dst, const void* src) {
    asm volatile("cp.async.cg.shared.global [%0], [%1], 16;"
                 :: "r"(dst), "l"(src) : "memory");
}
__device__ __forceinline__ void ldsm4(uint32_t* r, uint32_t addr) {
    asm volatile("ldmatrix.sync.aligned.m8n8.x4.shared.b16 {%0,%1,%2,%3}, [%4];"
                 : "=r"(r[0]), "=r"(r[1]), "=r"(r[2]), "=r"(r[3]) : "r"(addr));
}
__device__ __forceinline__ void mma_f16(float* c, const uint32_t* a,
                                        uint32_t b0, uint32_t b1) {
    asm volatile(
        "mma.sync.aligned.m16n8k16.row.col.f32.f16.f16.f32 "
        "{%0,%1,%2,%3}, {%4,%5,%6,%7}, {%8,%9}, {%0,%1,%2,%3};"
        : "+f"(c[0]), "+f"(c[1]), "+f"(c[2]), "+f"(c[3])
        : "r"(a[0]), "r"(a[1]), "r"(a[2]), "r"(a[3]), "r"(b0), "r"(b1));
}

#define BKC 32
#define SKB 80                        // smem row stride bytes (40 halves)

// ---------------------------------------------------------------------------
// gemm2<MT>: fp16 NT GEMM (1-term): C[bz][M,N] = A @ B^T (+bias)
// MT = m-subtiles (16 rows) per warp: MT=4 -> CTA 128x128, MT=2 -> CTA 64x128.
// A fp16 plane (lda=K), B fp16 plane (row stride ldb).
// Output fp16 (F16OUT) or fp32.  bias[bz*sBias + col].
// BK=32, 8 warps (2 x 4 warp grid), 2-stage cp.async, 256 threads, 2 CTAs/SM.
// ---------------------------------------------------------------------------
template<int MT, bool F16OUT>
__global__ void __launch_bounds__(256, 2) gemm2(
    const __half* __restrict__ Ap, long sA,
    const __half* __restrict__ Bp, long sB, int ldb,
    float* __restrict__ Cf, __half* __restrict__ Ch, long sC,
    int N, int K,
    const float* __restrict__ bias, long sBias)
{
    constexpr int BM      = MT * 32;            // CTA rows
    constexpr int PLANE_A = BM * SKB;
    constexpr int PLANE_BB = 128 * SKB;
    constexpr int STAGE   = PLANE_A + PLANE_BB;

    extern __shared__ char smc[];
    const uint32_t smb = (uint32_t)__cvta_generic_to_shared(smc);

    const int tid  = threadIdx.x;
    const int wid  = tid >> 5;
    const int lane = tid & 31;
    const int wm   = wid >> 2;       // 0..1
    const int wn   = wid & 3;        // 0..3
    const int gq   = lane >> 2;
    const int tg   = lane & 3;

    const int mtile = blockIdx.y * BM;
    const int ntile = blockIdx.x * 128;
    const int bz    = blockIdx.z;
    Ap += (long)bz * sA;
    Bp += (long)bz * sB;

    const int nch = K >> 5;

    float acc[MT][4][4];
#pragma unroll
    for (int i = 0; i < MT; i++)
#pragma unroll
        for (int j = 0; j < 4; j++)
#pragma unroll
            for (int q = 0; q < 4; q++) acc[i][j][q] = 0.f;

    const int lrow = tid >> 2;
    const int lseg = tid & 3;
    const long aoff = (long)(mtile + lrow) * K + lseg * 8;
    const long boff = (long)(ntile + lrow) * ldb + lseg * 8;
    const long ahalf = (long)64 * K;
    const long bhalf = (long)64 * ldb;
    const uint32_t sdst = lrow * SKB + lseg * 16;
    const uint32_t shalf = 64 * SKB;

    auto load_chunk = [&](int c, int s) {
        const long kofs = (long)c * BKC;
        const uint32_t sb = smb + s * STAGE + sdst;
        cp16(sb, Ap + aoff + kofs);
        if (MT == 4)
            cp16(sb + shalf, Ap + aoff + ahalf + kofs);
        cp16(sb + PLANE_A,          Bp + boff + kofs);
        cp16(sb + PLANE_A + shalf,  Bp + boff + bhalf + kofs);
    };

    load_chunk(0, 0);
    asm volatile("cp.async.commit_group;" ::: "memory");

    const int lr = (lane & 7) + ((lane >> 3) & 1) * 8;
    const int lc = ((lane >> 4) & 1) * 16;

    for (int c = 0; c < nch; c++) {
        const int s = c & 1;
        if (c + 1 < nch) {
            load_chunk(c + 1, s ^ 1);
            asm volatile("cp.async.commit_group;" ::: "memory");
            asm volatile("cp.async.wait_group 1;" ::: "memory");
        } else {
            asm volatile("cp.async.wait_group 0;" ::: "memory");
        }
        __syncthreads();
        const uint32_t stb = smb + s * STAGE;

#pragma unroll
        for (int kk = 0; kk < 2; kk++) {
            uint32_t bh[2][4];
#pragma unroll
            for (int h = 0; h < 2; h++) {
                uint32_t bd = stb + PLANE_A
                            + (uint32_t)(wn * 32 + h * 16 + lr) * SKB + kk * 32 + lc;
                ldsm4(bh[h], bd);
            }
#pragma unroll
            for (int mp = 0; mp < MT / 2; mp++) {
                uint32_t ah[2][4];
#pragma unroll
                for (int m2 = 0; m2 < 2; m2++) {
                    uint32_t ad = stb
                        + (uint32_t)(wm * (MT * 16) + (mp * 2 + m2) * 16 + lr) * SKB
                        + kk * 32 + lc;
                    ldsm4(ah[m2], ad);
                }
#pragma unroll
                for (int m2 = 0; m2 < 2; m2++)
#pragma unroll
                    for (int h = 0; h < 2; h++)
#pragma unroll
                        for (int j = 0; j < 2; j++)
                            mma_f16(acc[mp * 2 + m2][h * 2 + j],
                                    ah[m2], bh[h][j], bh[h][j + 2]);
            }
        }
        __syncthreads();
    }

#pragma unroll
    for (int mt = 0; mt < MT; mt++) {
        const int r0 = mtile + wm * (MT * 16) + mt * 16 + gq;
#pragma unroll
        for (int nt = 0; nt < 4; nt++) {
            const int col = ntile + wn * 32 + nt * 8 + tg * 2;
            float bx = 0.f, by = 0.f;
            if (bias != nullptr) {
                float2 bb = *(const float2*)(bias + bz * sBias + col);
                bx = bb.x; by = bb.y;
            }
            float o00 = acc[mt][nt][0] + bx;
            float o01 = acc[mt][nt][1] + by;
            float o10 = acc[mt][nt][2] + bx;
            float o11 = acc[mt][nt][3] + by;
            const long i0 = (long)bz * sC + (long)r0 * N + col;
            const long i1 = i0 + (long)8 * N;
            if (F16OUT) {
                __half2 p0, p1;
                p0.x = __float2half_rn(o00); p0.y = __float2half_rn(o01);
                p1.x = __float2half_rn(o10); p1.y = __float2half_rn(o11);
                *(__half2*)(Ch + i0) = p0;
                *(__half2*)(Ch + i1) = p1;
            } else {
                *(float2*)(Cf + i0) = make_float2(o00, o01);
                *(float2*)(Cf + i1) = make_float2(o10, o11);
            }
        }
    }
}

#define GSMEM_G4 (2 * (128 * SKB + 128 * SKB))   // 40960
#define GSMEM_G2 (2 * (64 * SKB + 128 * SKB))    // 30720

// ---------------------------------------------------------------------------
// sgemm_softmax: fused scores + masked softmax (BK=32, SKB=80).
// W[bz][64 rows][256] = softmax_row( q @ EQ^T + sb - 1e5*mask ) * d^-0.5
// ---------------------------------------------------------------------------
#define APL_B (64 * SKB)              // 5120 B
#define BPL_B (256 * SKB)             // 20480 B
#define STG_F (APL_B + BPL_B)         // 25600 B
#define GSMEM_F (2 * STG_F)           // 51200 B

__global__ void __launch_bounds__(256, 2) sgemm_softmax(
    const __half* __restrict__ Q,
    const __half* __restrict__ EQEO,
    const float* __restrict__ sb,
    const int* __restrict__ idx,
    __half* __restrict__ Wout)
{
    extern __shared__ char smc[];
    const uint32_t smb = (uint32_t)__cvta_generic_to_shared(smc);
    __shared__ float redm[64][9];
    __shared__ float reds[64][9];

    const int tid  = threadIdx.x;
    const int wid  = tid >> 5;
    const int lane = tid & 31;
    const int gq   = lane >> 2;
    const int tg   = lane & 3;

    const int mtile = blockIdx.y * 64;
    const int bz    = blockIdx.z;
    const int K = D_MODEL, ldb = 2048;

    const __half* A = Q    + (long)bz * LQ * D_MODEL;
    const __half* B = EQEO + (long)bz * NBE * 2048;

    float acc[4][4][4];
#pragma unroll
    for (int i = 0; i < 4; i++)
#pragma unroll
        for (int j = 0; j < 4; j++)
#pragma unroll
            for (int q = 0; q < 4; q++) acc[i][j][q] = 0.f;

    const int lrow = tid >> 2;
    const int lseg = tid & 3;
    const long aoff = (long)(mtile + lrow) * K + lseg * 8;
    const long boff = (long)lrow * ldb + lseg * 8;
    const uint32_t sdst = lrow * SKB + lseg * 16;
    const uint32_t s64 = 64 * SKB;

    auto load_chunk = [&](int c, int s) {
        const long kofs = (long)c * BKC;
        const uint32_t sbs = smb + s * STG_F + sdst;
        cp16(sbs, A + aoff + kofs);
        const uint32_t bb = sbs + APL_B;
        cp16(bb,           B + boff + kofs);
        cp16(bb + s64,     B + boff + (long)64  * ldb + kofs);
        cp16(bb + 2 * s64, B + boff + (long)128 * ldb + kofs);
        cp16(bb + 3 * s64, B + boff + (long)192 * ldb + kofs);
    };

    load_chunk(0, 0);
    asm volatile("cp.async.commit_group;" ::: "memory");

    const int lr = (lane & 7) + ((lane >> 3) & 1) * 8;
    const int lc = ((lane >> 4) & 1) * 16;
    const int nch = K >> 5;

    for (int c = 0; c < nch; c++) {
        const int s = c & 1;
        if (c + 1 < nch) {
            load_chunk(c + 1, s ^ 1);
            asm volatile("cp.async.commit_group;" ::: "memory");
            asm volatile("cp.async.wait_group 1;" ::: "memory");
        } else {
            asm volatile("cp.async.wait_group 0;" ::: "memory");
        }
        __syncthreads();
        const uint32_t stb = smb + s * STG_F;

#pragma unroll
        for (int kk = 0; kk < 2; kk++) {
            uint32_t bh[2][4];
#pragma unroll
            for (int h = 0; h < 2; h++) {
                uint32_t bd = stb + APL_B
                            + (uint32_t)(wid * 32 + h * 16 + lr) * SKB + kk * 32 + lc;
                ldsm4(bh[h], bd);
            }
#pragma unroll
            for (int mp = 0; mp < 2; mp++) {
                uint32_t ah[2][4];
#pragma unroll
                for (int m2 = 0; m2 < 2; m2++) {
                    uint32_t ad = stb
                        + (uint32_t)((mp * 2 + m2) * 16 + lr) * SKB + kk * 32 + lc;
                    ldsm4(ah[m2], ad);
                }
#pragma unroll
                for (int m2 = 0; m2 < 2; m2++)
#pragma unroll
                    for (int h = 0; h < 2; h++)
#pragma unroll
                        for (int j = 0; j < 2; j++)
                            mma_f16(acc[mp * 2 + m2][h * 2 + j],
                                    ah[m2], bh[h][j], bh[h][j + 2]);
            }
        }
        __syncthreads();
    }

    // ---- fused masked softmax epilogue ----
    const float* sbb = sb + bz * NBE;
    const int*  idxb = idx + bz * NBE;

#pragma unroll
    for (int nt = 0; nt < 4; nt++) {
        const int col = wid * 32 + nt * 8 + tg * 2;
        float2 bb = *(const float2*)(sbb + col);
        bool m0 = idxb[col] < 0;
        bool m1 = idxb[col + 1] < 0;
#pragma unroll
        for (int mt = 0; mt < 4; mt++) {
            acc[mt][nt][0] = m0 ? -100000.f : acc[mt][nt][0] + bb.x;
            acc[mt][nt][1] = m1 ? -100000.f : acc[mt][nt][1] + bb.y;
            acc[mt][nt][2] = m0 ? -100000.f : acc[mt][nt][2] + bb.x;
            acc[mt][nt][3] = m1 ? -100000.f : acc[mt][nt][3] + bb.y;
        }
    }

#pragma unroll
    for (int mt = 0; mt < 4; mt++)
#pragma unroll
        for (int rh = 0; rh < 2; rh++) {
            float m = -3.4e38f;
#pragma unroll
            for (int nt = 0; nt < 4; nt++) {
                m = fmaxf(m, acc[mt][nt][rh * 2]);
                m = fmaxf(m, acc[mt][nt][rh * 2 + 1]);
            }
            m = fmaxf(m, __shfl_xor_sync(0xffffffffu, m, 1));
            m = fmaxf(m, __shfl_xor_sync(0xffffffffu, m, 2));
            if (tg == 0) redm[mt * 16 + rh * 8 + gq][wid] = m;
        }
    __syncthreads();

#pragma unroll
    for (int mt = 0; mt < 4; mt++)
#pragma unroll
        for (int rh = 0; rh < 2; rh++) {
            const int rl = mt * 16 + rh * 8 + gq;
            float mall = redm[rl][0];
#pragma unroll
            for (int w = 1; w < 8; w++) mall = fmaxf(mall, redm[rl][w]);
            float ssum = 0.f;
#pragma unroll
            for (int nt = 0; nt < 4; nt++) {
                float e0 = expf(acc[mt][nt][rh * 2]     - mall);
                float e1 = expf(acc[mt][nt][rh * 2 + 1] - mall);
                acc[mt][nt][rh * 2]     = e0;
                acc[mt][nt][rh * 2 + 1] = e1;
                ssum += e0 + e1;
            }
            ssum += __shfl_xor_sync(0xffffffffu, ssum, 1);
            ssum += __shfl_xor_sync(0xffffffffu, ssum, 2);
            if (tg == 0) reds[rl][wid] = ssum;
        }
    __syncthreads();

#pragma unroll
    for (int mt = 0; mt < 4; mt++)
#pragma unroll
        for (int rh = 0; rh < 2; rh++) {
            const int rl = mt * 16 + rh * 8 + gq;
            float sum = reds[rl][0];
#pragma unroll
            for (int w = 1; w < 8; w++) sum += reds[rl][w];
            const float inv = 0.03125f / sum;
            const long rowoff = (long)(bz * LQ + mtile + rl) * NBE;
#pragma unroll
            for (int nt = 0; nt < 4; nt++) {
                const int col = wid * 32 + nt * 8 + tg * 2;
                __half2 p;
                p.x = __float2half_rn(acc[mt][nt][rh * 2]     * inv);
                p.y = __float2half_rn(acc[mt][nt][rh * 2 + 1] * inv);
                *(__half2*)(Wout + rowoff + col) = p;
            }
        }
}

// ---------------------------------------------------------------------------
// prep_all: merged input conversion kernel (one launch).
//   blocks [0, 16384)       : query fp32 -> qh fp16
//   blocks [16384, 17408)   : WO fp32 -> A12h/A12l rows 1024..2047 (split)
//   blocks [17408, 18432)   : WQ -> split+transpose into A12 rows 0..1023
//   blocks [18432, 19456)   : WK -> split+transpose into WKT
// ---------------------------------------------------------------------------
__global__ void prep_all(const float* __restrict__ query,
                         const float* __restrict__ WO,
                         const float* __restrict__ WQ,
                         const float* __restrict__ WK,
                         __half* __restrict__ qh,
                         __half* __restrict__ A12h, __half* __restrict__ A12l,
                         __half* __restrict__ WKTh, __half* __restrict__ WKTl)
{
    __shared__ float t[32][33];
    const int b   = blockIdx.x;
    const int tid = threadIdx.x;
    const long DD = (long)D_MODEL * D_MODEL;

    if (b < 16384) {
        const int i = b * 256 + tid;
        float4 v = ((const float4*)query)[i];
        __half hh[4];
        hh[0] = __float2half_rn(v.x); hh[1] = __float2half_rn(v.y);
        hh[2] = __float2half_rn(v.z); hh[3] = __float2half_rn(v.w);
        ((uint2*)qh)[i] = *(uint2*)hh;
    } else if (b < 17408) {
        const int i = (b - 16384) * 256 + tid;
        float4 v = ((const float4*)WO)[i];
        __half hh[4], ll[4];
        split1h(v.x, hh[0], ll[0]); split1h(v.y, hh[1], ll[1]);
        split1h(v.z, hh[2], ll[2]); split1h(v.w, hh[3], ll[3]);
        ((uint2*)(A12h + DD))[i] = *(uint2*)hh;
        ((uint2*)(A12l + DD))[i] = *(uint2*)ll;
    } else {
        const bool isWK = b >= 18432;
        const int bb = isWK ? b - 18432 : b - 17408;
        const float* W = isWK ? WK : WQ;
        __half* Th = isWK ? WKTh : A12h;
        __half* Tl = isWK ? WKTl : A12l;
        const int c0 = (bb & 31) * 32;
        const int r0 = (bb >> 5) * 32;
        const int tx = tid & 31, ty = tid >> 5;
#pragma unroll
        for (int i = 0; i < 32; i += 8)
            t[ty + i][tx] = W[(long)(r0 + ty + i) * D_MODEL + c0 + tx];
        __syncthreads();
#pragma unroll
        for (int i = 0; i < 32; i += 8) {
            float v = t[tx][ty + i];
            __half h, l;
            split1h(v, h, l);
            const long o = (long)(c0 + ty + i) * D_MODEL + r0 + tx;
            Th[o] = h;  Tl[o] = l;
        }
    }
}

// ---------------------------------------------------------------------------
// prep_vec: b2[0:1024]=bK@WQ, b2[1024:2048]=bK@WO^T, vb[0:1024]=WK^T bQ,
// vb[1024]=bQ.bK.  One block per output element.  (hi+lo planes, exact)
// ---------------------------------------------------------------------------
__global__ void prep_vec(const __half* __restrict__ A12h,
                         const __half* __restrict__ A12l,
                         const float* __restrict__ WO,
                         const __half* __restrict__ WKTh,
                         const __half* __restrict__ WKTl,
                         const float* __restrict__ bK,
                         const float* __restrict__ bQ,
                         float* __restrict__ b2, float* __restrict__ vb)
{
    const int n = blockIdx.x;
    const int t = threadIdx.x;
    float s = 0.f;

    if (n < 1024) {
        const uint2 h2 = ((const uint2*)(A12h + (long)n * D_MODEL))[t];
        const uint2 l2 = ((const uint2*)(A12l + (long)n * D_MODEL))[t];
        const __half* hp = (const __half*)&h2;
        const __half* lp = (const __half*)&l2;
        float4 b = ((const float4*)bK)[t];
        s = (__half2float(hp[0]) + __half2float(lp[0])) * b.x
          + (__half2float(hp[1]) + __half2float(lp[1])) * b.y
          + (__half2float(hp[2]) + __half2float(lp[2])) * b.z
          + (__half2float(hp[3]) + __half2float(lp[3])) * b.w;
    } else if (n < 2048) {
        float4 w = ((const float4*)(WO + (long)(n - 1024) * D_MODEL))[t];
        float4 b = ((const float4*)bK)[t];
        s = w.x * b.x + w.y * b.y + w.z * b.z + w.w * b.w;
    } else if (n < 3072) {
        const uint2 h2 = ((const uint2*)(WKTh + (long)(n - 2048) * D_MODEL))[t];
        const uint2 l2 = ((const uint2*)(WKTl + (long)(n - 2048) * D_MODEL))[t];
        const __half* hp = (const __half*)&h2;
        const __half* lp = (const __half*)&l2;
        float4 b = ((const float4*)bQ)[t];
        s = (__half2float(hp[0]) + __half2float(lp[0])) * b.x
          + (__half2float(hp[1]) + __half2float(lp[1])) * b.y
          + (__half2float(hp[2]) + __half2float(lp[2])) * b.z
          + (__half2float(hp[3]) + __half2float(lp[3])) * b.w;
    } else {
        float4 q = ((const float4*)bQ)[t];
        float4 b = ((const float4*)bK)[t];
        s = q.x * b.x + q.y * b.y + q.z * b.z + q.w * b.w;
    }

    __shared__ float red[8];
#pragma unroll
    for (int o = 16; o; o >>= 1) s += __shfl_xor_sync(0xffffffffu, s, o);
    if ((t & 31) == 0) red[t >> 5] = s;
    __syncthreads();
    if (t == 0) {
        float tot = 0.f;
#pragma unroll
        for (int i = 0; i < 8; i++) tot += red[i];
        if (n < 2048)      b2[n] = tot;
        else if (n < 3072) vb[n - 2048] = tot;
        else               vb[1024] = tot;
    }
}

// ---------------------------------------------------------------------------
// gather (single fp16 plane) + score-bias
// ---------------------------------------------------------------------------
__global__ void gather_sb(const float* __restrict__ E,
                          const int* __restrict__ idx,
                          const float* __restrict__ vb,
                          __half* __restrict__ Gh,
                          float* __restrict__ sb)
{
    const int r = blockIdx.x;
    int s = idx[r];
    if (s < 0) s = 0;
    const int i = threadIdx.x;
    float4 v = ((const float4*)(E + (long)s * D_MODEL))[i];
    __half hh[4];
    hh[0] = __float2half_rn(v.x); hh[1] = __float2half_rn(v.y);
    hh[2] = __float2half_rn(v.z); hh[3] = __float2half_rn(v.w);
    ((uint2*)(Gh + (long)r * D_MODEL))[i] = *(uint2*)hh;

    float4 w = ((const float4*)vb)[i];
    float d = v.x * w.x + v.y * w.y + v.z * w.z + v.w * w.w;
    __shared__ float red[8];
#pragma unroll
    for (int o = 16; o; o >>= 1) d += __shfl_xor_sync(0xffffffffu, d, o);
    if ((i & 31) == 0) red[i >> 5] = d;
    __syncthreads();
    if (i == 0) {
        float tot = vb[1024];
#pragma unroll
        for (int k = 0; k < 8; k++) tot += red[k];
        sb[r] = tot;
    }
}

// ---------------------------------------------------------------------------
// per-batch fp16 transpose of the EO half of EQEO -> EOT[b] (D x NBE)
// ---------------------------------------------------------------------------
__global__ void transpose_f16(const __half* __restrict__ EQEO,
                              __half* __restrict__ EOT)
{
    __shared__ __half t[32][34];
    const int b  = blockIdx.z;
    const int c0 = blockIdx.x * 32;
    const int r0 = blockIdx.y * 32;
    const int tx = threadIdx.x, ty = threadIdx.y;
#pragma unroll
    for (int i = 0; i < 32; i += 8)
        t[ty + i][tx] = EQEO[(long)(b * NBE + r0 + ty + i) * 2048 + 1024 + c0 + tx];
    __syncthreads();
#pragma unroll
    for (int i = 0; i < 32; i += 8)
        EOT[(long)b * NBE * D_MODEL + (long)(c0 + ty + i) * NBE + r0 + tx]
            = t[tx][ty + i];
}

// ---------------------------------------------------------------------------
// Row LayerNorm over D=1024 reading fp16 input (biased var, eps=1e-5).
// ---------------------------------------------------------------------------
__global__ void layernorm_h(const __half* __restrict__ X,
                            const float* __restrict__ g,
                            const float* __restrict__ b,
                            float* __restrict__ O)
{
    const int row = blockIdx.x;
    const int t   = threadIdx.x;

    const uint2 x2 = ((const uint2*)(X + (long)row * D_MODEL))[t];
    const __half* xp = (const __half*)&x2;
    float v0 = __half2float(xp[0]), v1 = __half2float(xp[1]);
    float v2 = __half2float(xp[2]), v3 = __half2float(xp[3]);

    float s  = v0 + v1 + v2 + v3;
    float sq = v0 * v0 + v1 * v1 + v2 * v2 + v3 * v3;

    __shared__ float rs[8], rq[8];
#pragma unroll
    for (int o = 16; o; o >>= 1) {
        s  += __shfl_xor_sync(0xffffffffu, s,  o);
        sq += __shfl_xor_sync(0xffffffffu, sq, o);
    }
    if ((t & 31) == 0) { rs[t >> 5] = s; rq[t >> 5] = sq; }
    __syncthreads();
    float S = 0.f, Q = 0.f;
#pragma unroll
    for (int i = 0; i < 8; i++) { S += rs[i]; Q += rq[i]; }

    float mu  = S * (1.f / 1024.f);
    float var = Q * (1.f / 1024.f) - mu * mu;
    float inv = rsqrtf(var + 1e-5f);

    float4 gg = *(const float4*)(g + t * 4);
    float4 bb = *(const float4*)(b + t * 4);
    float4 o;
    o.x = (v0 - mu) * inv * gg.x + bb.x;
    o.y = (v1 - mu) * inv * gg.y + bb.y;
    o.z = (v2 - mu) * inv * gg.z + bb.z;
    o.w = (v3 - mu) * inv * gg.w + bb.w;
    *(float4*)(O + (long)row * D_MODEL + t * 4) = o;
}

// ---------------------------------------------------------------------------
extern "C" void kernel_launch(void* const* d_in, const int* in_sizes, int n_in,
                              void* d_out, int out_size)
{
    const float* query   = (const float*)d_in[0];
    const float* ent_emb = (const float*)d_in[1];
    const int*   idx     = (const int*)  d_in[2];
    const float* WQ_w = (const float*)d_in[4];
    const float* WQ_b = (const float*)d_in[5];
    const float* WK_w = (const float*)d_in[6];
    const float* WK_b = (const float*)d_in[7];
    const float* WO_w = (const float*)d_in[8];
    const float* WO_b = (const float*)d_in[9];
    const float* ln_g = (const float*)d_in[10];
    const float* ln_b = (const float*)d_in[11];
    float* out = (float*)d_out;

    __half *qh, *A12h, *A12l, *WKTh, *WKTl, *Gh, *T12, *EQEO, *EOT, *Wh, *Ph;
    float *sb, *vb, *b2;
    cudaGetSymbolAddress((void**)&qh,   g_qh);
    cudaGetSymbolAddress((void**)&A12h, g_A12h); cudaGetSymbolAddress((void**)&A12l, g_A12l);
    cudaGetSymbolAddress((void**)&WKTh, g_WKTh); cudaGetSymbolAddress((void**)&WKTl, g_WKTl);
    cudaGetSymbolAddress((void**)&Gh,   g_Gh);
    cudaGetSymbolAddress((void**)&T12,  g_T12);
    cudaGetSymbolAddress((void**)&EQEO, g_EQEO);
    cudaGetSymbolAddress((void**)&EOT,  g_EOT);
    cudaGetSymbolAddress((void**)&Wh,   g_Wh);
    cudaGetSymbolAddress((void**)&Ph,   g_Ph);
    cudaGetSymbolAddress((void**)&sb,   g_sb);
    cudaGetSymbolAddress((void**)&vb,   g_vb);
    cudaGetSymbolAddress((void**)&b2,   g_b2);

    cudaFuncSetAttribute((const void*)gemm2<4, true >,
        cudaFuncAttributeMaxDynamicSharedMemorySize, GSMEM_G4);
    cudaFuncSetAttribute((const void*)gemm2<2, true >,
        cudaFuncAttributeMaxDynamicSharedMemorySize, GSMEM_G2);
    cudaFuncSetAttribute((const void*)sgemm_softmax,
        cudaFuncAttributeMaxDynamicSharedMemorySize, GSMEM_F);

    // 0. merged input preprocessing
    prep_all<<<19456, 256>>>(query, WO_w, WQ_w, WK_w,
                             qh, A12h, A12l, WKTh, WKTl);
    prep_vec<<<3073, 256>>>(A12h, A12l, WO_w, WKTh, WKTl, WK_b, WQ_b, b2, vb);
    gather_sb<<<MB, 256>>>(ent_emb, idx, vb, Gh, sb);

    // 1. [T1;T2] = [WQ^T;WO] @ WK  -- 64-row tiles -> 256 CTAs (occupancy fix)
    gemm2<2, true><<<dim3(8, 32, 1), 256, GSMEM_G2>>>(
        A12h, 0, WKTh, 0, D_MODEL, nullptr, T12, 0,
        D_MODEL, D_MODEL, nullptr, 0);

    // 2. EQEO = G @ [T1;T2]^T + bias2   [4096 x 2048 x 1024]
    gemm2<4, true><<<dim3(16, 32, 1), 256, GSMEM_G4>>>(
        Gh, 0, T12, 0, D_MODEL, nullptr, EQEO, 0,
        2048, D_MODEL, b2, 0);

    // 3. fused scores + masked softmax -> fp16 weights
    sgemm_softmax<<<dim3(1, 16, BATCH), 256, GSMEM_F>>>(
        qh, EQEO, sb, idx, Wh);

    // 4. EOT[b] = EO[b]^T
    transpose_f16<<<dim3(32, 8, BATCH), dim3(32, 8)>>>(EQEO, EOT);

    // 5. P[b] = W[b] @ EOT[b]^T + bO  -> fp16
    gemm2<4, true><<<dim3(8, 8, BATCH), 256, GSMEM_G4>>>(
        Wh, (long)LQ * NBE, EOT, (long)D_MODEL * NBE, NBE,
        nullptr, Ph, (long)LQ * D_MODEL, D_MODEL, NBE, WO_b, 0);

    // 6. LayerNorm (fp16 in) -> fp32 out
    layernorm_h<<<ML, 256>>>(Ph, ln_g, ln_b, out);
}

// round 17
// speedup vs baseline: 1.1443x; 1.0107x over previous
#include <cuda_runtime.h>
#include <cuda_bf16.h>
#include <cuda_fp16.h>
#include <cstdint>

// ---------------------------------------------------------------------------
// Problem constants
// ---------------------------------------------------------------------------
#define D_MODEL 1024
#define BATCH   16
#define LQ      1024
#define NBE     256
#define ML (BATCH * LQ)    // 16384
#define MB (BATCH * NBE)   // 4096

// ---------------------------------------------------------------------------
// Scratch (__device__ globals; no allocation anywhere)
// ---------------------------------------------------------------------------
__device__ __half  g_qh  [ML * D_MODEL];                 // query fp16 (1 plane)
__device__ __half  g_A12h[2048 * D_MODEL];               // [WQ^T ; WO] hi plane
__device__ __half  g_A12l[2048 * D_MODEL];               // lo plane (bias vectors only)
__device__ __half  g_WKTh[D_MODEL * D_MODEL];            // WK^T hi
__device__ __half  g_WKTl[D_MODEL * D_MODEL];            // WK^T lo (bias vectors only)
__device__ __half  g_Gh  [MB * D_MODEL];                 // gathered ents (1 plane)
__device__ __half  g_T12 [2048 * D_MODEL];               // [T1; T2] fp16
__device__ __half  g_EQ  [MB * D_MODEL];                 // EQ fp16
__device__ __half  g_EOT [MB * D_MODEL];                 // EO^T per batch (D x NBE)
__device__ float   g_sb  [MB];                           // bQ.ENT score bias
__device__ float   g_vb  [1025];                         // WK^T bQ, [1024]=bQ.bK
__device__ float   g_b2  [2048];                         // [bK@WQ | bK@WO^T]
__device__ __half  g_Wh  [ML * NBE];                     // softmax wts fp16 (1 plane)
__device__ __half  g_Ph  [ML * D_MODEL];                 // pre-LN fp16

// ---------------------------------------------------------------------------
// Helpers
// ---------------------------------------------------------------------------
__device__ __forceinline__ void split1h(float x, __half& h, __half& l) {
    h = __float2half_rn(x);
    l = __float2half_rn(x - __half2float(h));
}

__device__ __forceinline__ void cp16(uint32_t dst, const void* src) {
    asm volatile("cp.async.cg.shared.global [%0], [%1], 16;"
                 :: "r"(dst), "l"(src) : "memory");
}
__device__ __forceinline__ void ldsm4(uint32_t* r, uint32_t addr) {
    asm volatile("ldmatrix.sync.aligned.m8n8.x4.shared.b16 {%0,%1,%2,%3}, [%4];"
                 : "=r"(r[0]), "=r"(r[1]), "=r"(r[2]), "=r"(r[3]) : "r"(addr));
}
__device__ __forceinline__ void mma_f16(float* c, const uint32_t* a,
                                        uint32_t b0, uint32_t b1) {
    asm volatile(
        "mma.sync.aligned.m16n8k16.row.col.f32.f16.f16.f32 "
        "{%0,%1,%2,%3}, {%4,%5,%6,%7}, {%8,%9}, {%0,%1,%2,%3};"
        : "+f"(c[0]), "+f"(c[1]), "+f"(c[2]), "+f"(c[3])
        : "r"(a[0]), "r"(a[1]), "r"(a[2]), "r"(a[3]), "r"(b0), "r"(b1));
}

#define BKC 32
#define SKB 80                        // smem row stride bytes (40 halves)

// ---------------------------------------------------------------------------
// gemm2<MT, F16OUT, ROWBIAS>: fp16 NT GEMM (1-term): C[bz][M,N] = A @ B^T (+b)
// MT m-subtiles per warp (MT=4 -> CTA 128x128, MT=2 -> 64x128).
// ROWBIAS: bias indexed by output ROW (bias[r]); else by column (bias[bz*sBias+col]).
// BK=32, 8 warps (2x4), 2-stage cp.async, 256 threads, 2 CTAs/SM.
// ---------------------------------------------------------------------------
template<int MT, bool F16OUT, bool ROWBIAS = false>
__global__ void __launch_bounds__(256, 2) gemm2(
    const __half* __restrict__ Ap, long sA,
    const __half* __restrict__ Bp, long sB, int ldb,
    float* __restrict__ Cf, __half* __restrict__ Ch, long sC,
    int N, int K,
    const float* __restrict__ bias, long sBias)
{
    constexpr int BM      = MT * 32;
    constexpr int PLANE_A = BM * SKB;
    constexpr int PLANE_BB = 128 * SKB;
    constexpr int STAGE   = PLANE_A + PLANE_BB;

    extern __shared__ char smc[];
    const uint32_t smb = (uint32_t)__cvta_generic_to_shared(smc);

    const int tid  = threadIdx.x;
    const int wid  = tid >> 5;
    const int lane = tid & 31;
    const int wm   = wid >> 2;
    const int wn   = wid & 3;
    const int gq   = lane >> 2;
    const int tg   = lane & 3;

    const int mtile = blockIdx.y * BM;
    const int ntile = blockIdx.x * 128;
    const int bz    = blockIdx.z;
    Ap += (long)bz * sA;
    Bp += (long)bz * sB;

    const int nch = K >> 5;

    float acc[MT][4][4];
#pragma unroll
    for (int i = 0; i < MT; i++)
#pragma unroll
        for (int j = 0; j < 4; j++)
#pragma unroll
            for (int q = 0; q < 4; q++) acc[i][j][q] = 0.f;

    const int lrow = tid >> 2;
    const int lseg = tid & 3;
    const long aoff = (long)(mtile + lrow) * K + lseg * 8;
    const long boff = (long)(ntile + lrow) * ldb + lseg * 8;
    const long ahalf = (long)64 * K;
    const long bhalf = (long)64 * ldb;
    const uint32_t sdst = lrow * SKB + lseg * 16;
    const uint32_t shalf = 64 * SKB;

    auto load_chunk = [&](int c, int s) {
        const long kofs = (long)c * BKC;
        const uint32_t sb = smb + s * STAGE + sdst;
        cp16(sb, Ap + aoff + kofs);
        if (MT == 4)
            cp16(sb + shalf, Ap + aoff + ahalf + kofs);
        cp16(sb + PLANE_A,          Bp + boff + kofs);
        cp16(sb + PLANE_A + shalf,  Bp + boff + bhalf + kofs);
    };

    load_chunk(0, 0);
    asm volatile("cp.async.commit_group;" ::: "memory");

    const int lr = (lane & 7) + ((lane >> 3) & 1) * 8;
    const int lc = ((lane >> 4) & 1) * 16;

    for (int c = 0; c < nch; c++) {
        const int s = c & 1;
        if (c + 1 < nch) {
            load_chunk(c + 1, s ^ 1);
            asm volatile("cp.async.commit_group;" ::: "memory");
            asm volatile("cp.async.wait_group 1;" ::: "memory");
        } else {
            asm volatile("cp.async.wait_group 0;" ::: "memory");
        }
        __syncthreads();
        const uint32_t stb = smb + s * STAGE;

#pragma unroll
        for (int kk = 0; kk < 2; kk++) {
            uint32_t bh[2][4];
#pragma unroll
            for (int h = 0; h < 2; h++) {
                uint32_t bd = stb + PLANE_A
                            + (uint32_t)(wn * 32 + h * 16 + lr) * SKB + kk * 32 + lc;
                ldsm4(bh[h], bd);
            }
#pragma unroll
            for (int mp = 0; mp < MT / 2; mp++) {
                uint32_t ah[2][4];
#pragma unroll
                for (int m2 = 0; m2 < 2; m2++) {
                    uint32_t ad = stb
                        + (uint32_t)(wm * (MT * 16) + (mp * 2 + m2) * 16 + lr) * SKB
                        + kk * 32 + lc;
                    ldsm4(ah[m2], ad);
                }
#pragma unroll
                for (int m2 = 0; m2 < 2; m2++)
#pragma unroll
                    for (int h = 0; h < 2; h++)
#pragma unroll
                        for (int j = 0; j < 2; j++)
                            mma_f16(acc[mp * 2 + m2][h * 2 + j],
                                    ah[m2], bh[h][j], bh[h][j + 2]);
            }
        }
        __syncthreads();
    }

#pragma unroll
    for (int mt = 0; mt < MT; mt++) {
        const int r0 = mtile + wm * (MT * 16) + mt * 16 + gq;
        float rb0 = 0.f, rb8 = 0.f;
        if (ROWBIAS && bias != nullptr) {
            rb0 = bias[r0];
            rb8 = bias[r0 + 8];
        }
#pragma unroll
        for (int nt = 0; nt < 4; nt++) {
            const int col = ntile + wn * 32 + nt * 8 + tg * 2;
            float bx = 0.f, by = 0.f;
            if (!ROWBIAS && bias != nullptr) {
                float2 bb = *(const float2*)(bias + bz * sBias + col);
                bx = bb.x; by = bb.y;
            }
            float o00, o01, o10, o11;
            if (ROWBIAS) {
                o00 = acc[mt][nt][0] + rb0;
                o01 = acc[mt][nt][1] + rb0;
                o10 = acc[mt][nt][2] + rb8;
                o11 = acc[mt][nt][3] + rb8;
            } else {
                o00 = acc[mt][nt][0] + bx;
                o01 = acc[mt][nt][1] + by;
                o10 = acc[mt][nt][2] + bx;
                o11 = acc[mt][nt][3] + by;
            }
            const long i0 = (long)bz * sC + (long)r0 * N + col;
            const long i1 = i0 + (long)8 * N;
            if (F16OUT) {
                __half2 p0, p1;
                p0.x = __float2half_rn(o00); p0.y = __float2half_rn(o01);
                p1.x = __float2half_rn(o10); p1.y = __float2half_rn(o11);
                *(__half2*)(Ch + i0) = p0;
                *(__half2*)(Ch + i1) = p1;
            } else {
                *(float2*)(Cf + i0) = make_float2(o00, o01);
                *(float2*)(Cf + i1) = make_float2(o10, o11);
            }
        }
    }
}

#define GSMEM_G4 (2 * (128 * SKB + 128 * SKB))   // 40960
#define GSMEM_G2 (2 * (64 * SKB + 128 * SKB))    // 30720

// ---------------------------------------------------------------------------
// sgemm_softmax: fused scores + masked softmax (BK=32, SKB=80).
// W[bz][64 rows][256] = softmax_row( q @ EQ^T + sb - 1e5*mask ) * d^-0.5
// EQ layout: [MB, 1024] row-major, per-batch base bz*NBE*1024, ldb=1024.
// ---------------------------------------------------------------------------
#define APL_B (64 * SKB)              // 5120 B
#define BPL_B (256 * SKB)             // 20480 B
#define STG_F (APL_B + BPL_B)         // 25600 B
#define GSMEM_F (2 * STG_F)           // 51200 B

__global__ void __launch_bounds__(256, 2) sgemm_softmax(
    const __half* __restrict__ Q,
    const __half* __restrict__ EQ,
    const float* __restrict__ sb,
    const int* __restrict__ idx,
    __half* __restrict__ Wout)
{
    extern __shared__ char smc[];
    const uint32_t smb = (uint32_t)__cvta_generic_to_shared(smc);
    __shared__ float redm[64][9];
    __shared__ float reds[64][9];

    const int tid  = threadIdx.x;
    const int wid  = tid >> 5;
    const int lane = tid & 31;
    const int gq   = lane >> 2;
    const int tg   = lane & 3;

    const int mtile = blockIdx.y * 64;
    const int bz    = blockIdx.z;
    const int K = D_MODEL, ldb = D_MODEL;

    const __half* A = Q  + (long)bz * LQ * D_MODEL;
    const __half* B = EQ + (long)bz * NBE * D_MODEL;

    float acc[4][4][4];
#pragma unroll
    for (int i = 0; i < 4; i++)
#pragma unroll
        for (int j = 0; j < 4; j++)
#pragma unroll
            for (int q = 0; q < 4; q++) acc[i][j][q] = 0.f;

    const int lrow = tid >> 2;
    const int lseg = tid & 3;
    const long aoff = (long)(mtile + lrow) * K + lseg * 8;
    const long boff = (long)lrow * ldb + lseg * 8;
    const uint32_t sdst = lrow * SKB + lseg * 16;
    const uint32_t s64 = 64 * SKB;

    auto load_chunk = [&](int c, int s) {
        const long kofs = (long)c * BKC;
        const uint32_t sbs = smb + s * STG_F + sdst;
        cp16(sbs, A + aoff + kofs);
        const uint32_t bb = sbs + APL_B;
        cp16(bb,           B + boff + kofs);
        cp16(bb + s64,     B + boff + (long)64  * ldb + kofs);
        cp16(bb + 2 * s64, B + boff + (long)128 * ldb + kofs);
        cp16(bb + 3 * s64, B + boff + (long)192 * ldb + kofs);
    };

    load_chunk(0, 0);
    asm volatile("cp.async.commit_group;" ::: "memory");

    const int lr = (lane & 7) + ((lane >> 3) & 1) * 8;
    const int lc = ((lane >> 4) & 1) * 16;
    const int nch = K >> 5;

    for (int c = 0; c < nch; c++) {
        const int s = c & 1;
        if (c + 1 < nch) {
            load_chunk(c + 1, s ^ 1);
            asm volatile("cp.async.commit_group;" ::: "memory");
            asm volatile("cp.async.wait_group 1;" ::: "memory");
        } else {
            asm volatile("cp.async.wait_group 0;" ::: "memory");
        }
        __syncthreads();
        const uint32_t stb = smb + s * STG_F;

#pragma unroll
        for (int kk = 0; kk < 2; kk++) {
            uint32_t bh[2][4];
#pragma unroll
            for (int h = 0; h < 2; h++) {
                uint32_t bd = stb + APL_B
                            + (uint32_t)(wid * 32 + h * 16 + lr) * SKB + kk * 32 + lc;
                ldsm4(bh[h], bd);
            }
#pragma unroll
            for (int mp = 0; mp < 2; mp++) {
                uint32_t ah[2][4];
#pragma unroll
                for (int m2 = 0; m2 < 2; m2++) {
                    uint32_t ad = stb
                        + (uint32_t)((mp * 2 + m2) * 16 + lr) * SKB + kk * 32 + lc;
                    ldsm4(ah[m2], ad);
                }
#pragma unroll
                for (int m2 = 0; m2 < 2; m2++)
#pragma unroll
                    for (int h = 0; h < 2; h++)
#pragma unroll
                        for (int j = 0; j < 2; j++)
                            mma_f16(acc[mp * 2 + m2][h * 2 + j],
                                    ah[m2], bh[h][j], bh[h][j + 2]);
            }
        }
        __syncthreads();
    }

    // ---- fused masked softmax epilogue ----
    const float* sbb = sb + bz * NBE;
    const int*  idxb = idx + bz * NBE;

#pragma unroll
    for (int nt = 0; nt < 4; nt++) {
        const int col = wid * 32 + nt * 8 + tg * 2;
        float2 bb = *(const float2*)(sbb + col);
        bool m0 = idxb[col] < 0;
        bool m1 = idxb[col + 1] < 0;
#pragma unroll
        for (int mt = 0; mt < 4; mt++) {
            acc[mt][nt][0] = m0 ? -100000.f : acc[mt][nt][0] + bb.x;
            acc[mt][nt][1] = m1 ? -100000.f : acc[mt][nt][1] + bb.y;
            acc[mt][nt][2] = m0 ? -100000.f : acc[mt][nt][2] + bb.x;
            acc[mt][nt][3] = m1 ? -100000.f : acc[mt][nt][3] + bb.y;
        }
    }

#pragma unroll
    for (int mt = 0; mt < 4; mt++)
#pragma unroll
        for (int rh = 0; rh < 2; rh++) {
            float m = -3.4e38f;
#pragma unroll
            for (int nt = 0; nt < 4; nt++) {
                m = fmaxf(m, acc[mt][nt][rh * 2]);
                m = fmaxf(m, acc[mt][nt][rh * 2 + 1]);
            }
            m = fmaxf(m, __shfl_xor_sync(0xffffffffu, m, 1));
            m = fmaxf(m, __shfl_xor_sync(0xffffffffu, m, 2));
            if (tg == 0) redm[mt * 16 + rh * 8 + gq][wid] = m;
        }
    __syncthreads();

#pragma unroll
    for (int mt = 0; mt < 4; mt++)
#pragma unroll
        for (int rh = 0; rh < 2; rh++) {
            const int rl = mt * 16 + rh * 8 + gq;
            float mall = redm[rl][0];
#pragma unroll
            for (int w = 1; w < 8; w++) mall = fmaxf(mall, redm[rl][w]);
            float ssum = 0.f;
#pragma unroll
            for (int nt = 0; nt < 4; nt++) {
                float e0 = expf(acc[mt][nt][rh * 2]     - mall);
                float e1 = expf(acc[mt][nt][rh * 2 + 1] - mall);
                acc[mt][nt][rh * 2]     = e0;
                acc[mt][nt][rh * 2 + 1] = e1;
                ssum += e0 + e1;
            }
            ssum += __shfl_xor_sync(0xffffffffu, ssum, 1);
            ssum += __shfl_xor_sync(0xffffffffu, ssum, 2);
            if (tg == 0) reds[rl][wid] = ssum;
        }
    __syncthreads();

#pragma unroll
    for (int mt = 0; mt < 4; mt++)
#pragma unroll
        for (int rh = 0; rh < 2; rh++) {
            const int rl = mt * 16 + rh * 8 + gq;
            float sum = reds[rl][0];
#pragma unroll
            for (int w = 1; w < 8; w++) sum += reds[rl][w];
            const float inv = 0.03125f / sum;
            const long rowoff = (long)(bz * LQ + mtile + rl) * NBE;
#pragma unroll
            for (int nt = 0; nt < 4; nt++) {
                const int col = wid * 32 + nt * 8 + tg * 2;
                __half2 p;
                p.x = __float2half_rn(acc[mt][nt][rh * 2]     * inv);
                p.y = __float2half_rn(acc[mt][nt][rh * 2 + 1] * inv);
                *(__half2*)(Wout + rowoff + col) = p;
            }
        }
}

// ---------------------------------------------------------------------------
// prep_all: merged input conversion kernel (one launch).
// ---------------------------------------------------------------------------
__global__ void prep_all(const float* __restrict__ query,
                         const float* __restrict__ WO,
                         const float* __restrict__ WQ,
                         const float* __restrict__ WK,
                         __half* __restrict__ qh,
                         __half* __restrict__ A12h, __half* __restrict__ A12l,
                         __half* __restrict__ WKTh, __half* __restrict__ WKTl)
{
    __shared__ float t[32][33];
    const int b   = blockIdx.x;
    const int tid = threadIdx.x;
    const long DD = (long)D_MODEL * D_MODEL;

    if (b < 16384) {
        const int i = b * 256 + tid;
        float4 v = ((const float4*)query)[i];
        __half hh[4];
        hh[0] = __float2half_rn(v.x); hh[1] = __float2half_rn(v.y);
        hh[2] = __float2half_rn(v.z); hh[3] = __float2half_rn(v.w);
        ((uint2*)qh)[i] = *(uint2*)hh;
    } else if (b < 17408) {
        const int i = (b - 16384) * 256 + tid;
        float4 v = ((const float4*)WO)[i];
        __half hh[4], ll[4];
        split1h(v.x, hh[0], ll[0]); split1h(v.y, hh[1], ll[1]);
        split1h(v.z, hh[2], ll[2]); split1h(v.w, hh[3], ll[3]);
        ((uint2*)(A12h + DD))[i] = *(uint2*)hh;
        ((uint2*)(A12l + DD))[i] = *(uint2*)ll;
    } else {
        const bool isWK = b >= 18432;
        const int bb = isWK ? b - 18432 : b - 17408;
        const float* W = isWK ? WK : WQ;
        __half* Th = isWK ? WKTh : A12h;
        __half* Tl = isWK ? WKTl : A12l;
        const int c0 = (bb & 31) * 32;
        const int r0 = (bb >> 5) * 32;
        const int tx = tid & 31, ty = tid >> 5;
#pragma unroll
        for (int i = 0; i < 32; i += 8)
            t[ty + i][tx] = W[(long)(r0 + ty + i) * D_MODEL + c0 + tx];
        __syncthreads();
#pragma unroll
        for (int i = 0; i < 32; i += 8) {
            float v = t[tx][ty + i];
            __half h, l;
            split1h(v, h, l);
            const long o = (long)(c0 + ty + i) * D_MODEL + r0 + tx;
            Th[o] = h;  Tl[o] = l;
        }
    }
}

// ---------------------------------------------------------------------------
// prep_vec: b2[0:1024]=bK@WQ, b2[1024:2048]=bK@WO^T, vb[0:1024]=WK^T bQ,
// vb[1024]=bQ.bK.  One block per output element.  (hi+lo planes, exact)
// ---------------------------------------------------------------------------
__global__ void prep_vec(const __half* __restrict__ A12h,
                         const __half* __restrict__ A12l,
                         const float* __restrict__ WO,
                         const __half* __restrict__ WKTh,
                         const __half* __restrict__ WKTl,
                         const float* __restrict__ bK,
                         const float* __restrict__ bQ,
                         float* __restrict__ b2, float* __restrict__ vb)
{
    const int n = blockIdx.x;
    const int t = threadIdx.x;
    float s = 0.f;

    if (n < 1024) {
        const uint2 h2 = ((const uint2*)(A12h + (long)n * D_MODEL))[t];
        const uint2 l2 = ((const uint2*)(A12l + (long)n * D_MODEL))[t];
        const __half* hp = (const __half*)&h2;
        const __half* lp = (const __half*)&l2;
        float4 b = ((const float4*)bK)[t];
        s = (__half2float(hp[0]) + __half2float(lp[0])) * b.x
          + (__half2float(hp[1]) + __half2float(lp[1])) * b.y
          + (__half2float(hp[2]) + __half2float(lp[2])) * b.z
          + (__half2float(hp[3]) + __half2float(lp[3])) * b.w;
    } else if (n < 2048) {
        float4 w = ((const float4*)(WO + (long)(n - 1024) * D_MODEL))[t];
        float4 b = ((const float4*)bK)[t];
        s = w.x * b.x + w.y * b.y + w.z * b.z + w.w * b.w;
    } else if (n < 3072) {
        const uint2 h2 = ((const uint2*)(WKTh + (long)(n - 2048) * D_MODEL))[t];
        const uint2 l2 = ((const uint2*)(WKTl + (long)(n - 2048) * D_MODEL))[t];
        const __half* hp = (const __half*)&h2;
        const __half* lp = (const __half*)&l2;
        float4 b = ((const float4*)bQ)[t];
        s = (__half2float(hp[0]) + __half2float(lp[0])) * b.x
          + (__half2float(hp[1]) + __half2float(lp[1])) * b.y
          + (__half2float(hp[2]) + __half2float(lp[2])) * b.z
          + (__half2float(hp[3]) + __half2float(lp[3])) * b.w;
    } else {
        float4 q = ((const float4*)bQ)[t];
        float4 b = ((const float4*)bK)[t];
        s = q.x * b.x + q.y * b.y + q.z * b.z + q.w * b.w;
    }

    __shared__ float red[8];
#pragma unroll
    for (int o = 16; o; o >>= 1) s += __shfl_xor_sync(0xffffffffu, s, o);
    if ((t & 31) == 0) red[t >> 5] = s;
    __syncthreads();
    if (t == 0) {
        float tot = 0.f;
#pragma unroll
        for (int i = 0; i < 8; i++) tot += red[i];
        if (n < 2048)      b2[n] = tot;
        else if (n < 3072) vb[n - 2048] = tot;
        else               vb[1024] = tot;
    }
}

// ---------------------------------------------------------------------------
// gather (single fp16 plane) + score-bias
// ---------------------------------------------------------------------------
__global__ void gather_sb(const float* __restrict__ E,
                          const int* __restrict__ idx,
                          const float* __restrict__ vb,
                          __half* __restrict__ Gh,
                          float* __restrict__ sb)
{
    const int r = blockIdx.x;
    int s = idx[r];
    if (s < 0) s = 0;
    const int i = threadIdx.x;
    float4 v = ((const float4*)(E + (long)s * D_MODEL))[i];
    __half hh[4];
    hh[0] = __float2half_rn(v.x); hh[1] = __float2half_rn(v.y);
    hh[2] = __float2half_rn(v.z); hh[3] = __float2half_rn(v.w);
    ((uint2*)(Gh + (long)r * D_MODEL))[i] = *(uint2*)hh;

    float4 w = ((const float4*)vb)[i];
    float d = v.x * w.x + v.y * w.y + v.z * w.z + v.w * w.w;
    __shared__ float red[8];
#pragma unroll
    for (int o = 16; o; o >>= 1) d += __shfl_xor_sync(0xffffffffu, d, o);
    if ((i & 31) == 0) red[i >> 5] = d;
    __syncthreads();
    if (i == 0) {
        float tot = vb[1024];
#pragma unroll
        for (int k = 0; k < 8; k++) tot += red[k];
        sb[r] = tot;
    }
}

// ---------------------------------------------------------------------------
// Row LayerNorm over D=1024 reading fp16 input (biased var, eps=1e-5).
// ---------------------------------------------------------------------------
__global__ void layernorm_h(const __half* __restrict__ X,
                            const float* __restrict__ g,
                            const float* __restrict__ b,
                            float* __restrict__ O)
{
    const int row = blockIdx.x;
    const int t   = threadIdx.x;

    const uint2 x2 = ((const uint2*)(X + (long)row * D_MODEL))[t];
    const __half* xp = (const __half*)&x2;
    float v0 = __half2float(xp[0]), v1 = __half2float(xp[1]);
    float v2 = __half2float(xp[2]), v3 = __half2float(xp[3]);

    float s  = v0 + v1 + v2 + v3;
    float sq = v0 * v0 + v1 * v1 + v2 * v2 + v3 * v3;

    __shared__ float rs[8], rq[8];
#pragma unroll
    for (int o = 16; o; o >>= 1) {
        s  += __shfl_xor_sync(0xffffffffu, s,  o);
        sq += __shfl_xor_sync(0xffffffffu, sq, o);
    }
    if ((t & 31) == 0) { rs[t >> 5] = s; rq[t >> 5] = sq; }
    __syncthreads();
    float S = 0.f, Q = 0.f;
#pragma unroll
    for (int i = 0; i < 8; i++) { S += rs[i]; Q += rq[i]; }

    float mu  = S * (1.f / 1024.f);
    float var = Q * (1.f / 1024.f) - mu * mu;
    float inv = rsqrtf(var + 1e-5f);

    float4 gg = *(const float4*)(g + t * 4);
    float4 bb = *(const float4*)(b + t * 4);
    float4 o;
    o.x = (v0 - mu) * inv * gg.x + bb.x;
    o.y = (v1 - mu) * inv * gg.y + bb.y;
    o.z = (v2 - mu) * inv * gg.z + bb.z;
    o.w = (v3 - mu) * inv * gg.w + bb.w;
    *(float4*)(O + (long)row * D_MODEL + t * 4) = o;
}

// ---------------------------------------------------------------------------
extern "C" void kernel_launch(void* const* d_in, const int* in_sizes, int n_in,
                              void* d_out, int out_size)
{
    const float* query   = (const float*)d_in[0];
    const float* ent_emb = (const float*)d_in[1];
    const int*   idx     = (const int*)  d_in[2];
    const float* WQ_w = (const float*)d_in[4];
    const float* WQ_b = (const float*)d_in[5];
    const float* WK_w = (const float*)d_in[6];
    const float* WK_b = (const float*)d_in[7];
    const float* WO_w = (const float*)d_in[8];
    const float* WO_b = (const float*)d_in[9];
    const float* ln_g = (const float*)d_in[10];
    const float* ln_b = (const float*)d_in[11];
    float* out = (float*)d_out;

    __half *qh, *A12h, *A12l, *WKTh, *WKTl, *Gh, *T12, *EQ, *EOT, *Wh, *Ph;
    float *sb, *vb, *b2;
    cudaGetSymbolAddress((void**)&qh,   g_qh);
    cudaGetSymbolAddress((void**)&A12h, g_A12h); cudaGetSymbolAddress((void**)&A12l, g_A12l);
    cudaGetSymbolAddress((void**)&WKTh, g_WKTh); cudaGetSymbolAddress((void**)&WKTl, g_WKTl);
    cudaGetSymbolAddress((void**)&Gh,   g_Gh);
    cudaGetSymbolAddress((void**)&T12,  g_T12);
    cudaGetSymbolAddress((void**)&EQ,   g_EQ);
    cudaGetSymbolAddress((void**)&EOT,  g_EOT);
    cudaGetSymbolAddress((void**)&Wh,   g_Wh);
    cudaGetSymbolAddress((void**)&Ph,   g_Ph);
    cudaGetSymbolAddress((void**)&sb,   g_sb);
    cudaGetSymbolAddress((void**)&vb,   g_vb);
    cudaGetSymbolAddress((void**)&b2,   g_b2);

    cudaFuncSetAttribute((const void*)gemm2<4, true, false>,
        cudaFuncAttributeMaxDynamicSharedMemorySize, GSMEM_G4);
    cudaFuncSetAttribute((const void*)gemm2<4, true, true >,
        cudaFuncAttributeMaxDynamicSharedMemorySize, GSMEM_G4);
    cudaFuncSetAttribute((const void*)gemm2<2, true, false>,
        cudaFuncAttributeMaxDynamicSharedMemorySize, GSMEM_G2);
    cudaFuncSetAttribute((const void*)sgemm_softmax,
        cudaFuncAttributeMaxDynamicSharedMemorySize, GSMEM_F);

    const long DD = (long)D_MODEL * D_MODEL;

    // 0. merged input preprocessing
    prep_all<<<19456, 256>>>(query, WO_w, WQ_w, WK_w,
                             qh, A12h, A12l, WKTh, WKTl);
    prep_vec<<<3073, 256>>>(A12h, A12l, WO_w, WKTh, WKTl, WK_b, WQ_b, b2, vb);
    gather_sb<<<MB, 256>>>(ent_emb, idx, vb, Gh, sb);

    // 1. [T1;T2] = [WQ^T;WO] @ WK  (64-row tiles, 256 CTAs)
    gemm2<2, true, false><<<dim3(8, 32, 1), 256, GSMEM_G2>>>(
        A12h, 0, WKTh, 0, D_MODEL, nullptr, T12, 0,
        D_MODEL, D_MODEL, nullptr, 0);

    // 2a. EQ = G @ T1^T + b2[0:1024]   [4096 x 1024 x 1024]
    gemm2<4, true, false><<<dim3(8, 32, 1), 256, GSMEM_G4>>>(
        Gh, 0, T12, 0, D_MODEL, nullptr, EQ, 0,
        D_MODEL, D_MODEL, b2, 0);

    // 2b. EOT[b] = T2 @ G[b]^T + rowbias b2[1024:2048]   [16 x (1024 x 256 x 1024)]
    //     (= (G[b] @ T2^T)^T, transpose computed directly)
    gemm2<4, true, true><<<dim3(2, 8, BATCH), 256, GSMEM_G4>>>(
        T12 + DD, 0, Gh, (long)NBE * D_MODEL, D_MODEL,
        nullptr, EOT, (long)D_MODEL * NBE, NBE, D_MODEL, b2 + 1024, 0);

    // 3. fused scores + masked softmax -> fp16 weights
    sgemm_softmax<<<dim3(1, 16, BATCH), 256, GSMEM_F>>>(
        qh, EQ, sb, idx, Wh);

    // 4. P[b] = W[b] @ EOT[b]^T + bO  -> fp16
    gemm2<4, true, false><<<dim3(8, 8, BATCH), 256, GSMEM_G4>>>(
        Wh, (long)LQ * NBE, EOT, (long)D_MODEL * NBE, NBE,
        nullptr, Ph, (long)LQ * D_MODEL, D_MODEL, NBE, WO_b, 0);

    // 5. LayerNorm (fp16 in) -> fp32 out
    layernorm_h<<<ML, 256>>>(Ph, ln_g, ln_b, out);
}